// round 12
// baseline (speedup 1.0000x reference)
#include <cuda_runtime.h>
#include <cuda_bf16.h>
#include <cuda_fp16.h>
#include <cstdint>
#include <cstddef>

#define NB 4096
#define NS 544
#define NH 256
#define ND 128
#define NM 50000
#define NK 50
#define NSPLIT 4
#define SPLEN 12544      // 98 * 128
#define TILEN 128
#define NBLK 784         // 4 splits * 196 blocks of 64 keys
#define F_INF __int_as_float(0x7f800000)

// ---------------- scratch (static device globals; no allocations) ----------
__device__ float g_h[NB * NH];
__device__ float g_qpre[NB * ND];
__device__ float g_q[NB * ND];
__device__ float g_q2[NB];
__device__ float g_k2[NM];
__device__ float g_v1[NB * NH];
__device__ float g_v2[NB * ND];
__device__ float g_net[NB];
__device__ __half g_keysh[NM * ND];            // fp16 keys
__device__ __half g_dist[(size_t)NB * NM];     // 409.6 MB fp16 score matrix
__device__ __half g_tmin[(size_t)NB * NBLK];   // 6.4 MB block minima
__device__ int g_cand[NB * 64];

// ---------------- helpers ----------------
__device__ __forceinline__ uint32_t smem_u32(const void* p) {
    uint32_t a;
    asm("{ .reg .u64 t; cvta.to.shared.u64 t, %1; cvt.u32.u64 %0, t; }" : "=r"(a) : "l"(p));
    return a;
}
__device__ __forceinline__ void cp16(uint32_t dst, const void* src) {
    asm volatile("cp.async.ca.shared.global [%0], [%1], 16;\n" :: "r"(dst), "l"(src));
}
__device__ __forceinline__ float warp_allred(float v) {
#pragma unroll
    for (int o = 16; o; o >>= 1) v += __shfl_xor_sync(0xffffffffu, v, o);
    return v;
}
__device__ __forceinline__ void ldsm_x4(uint32_t& r0, uint32_t& r1, uint32_t& r2,
                                        uint32_t& r3, uint32_t addr) {
    asm volatile("ldmatrix.sync.aligned.m8n8.x4.shared.b16 {%0,%1,%2,%3}, [%4];"
                 : "=r"(r0), "=r"(r1), "=r"(r2), "=r"(r3) : "r"(addr));
}
// fp16 inputs, fp16 accumulate: 2 packed d-regs (d0: row r cols {c,c+1}; d1: row r+8)
__device__ __forceinline__ void mma_f16acc(uint32_t* c, const uint32_t* a,
                                           uint32_t b0, uint32_t b1) {
    asm volatile("mma.sync.aligned.m16n8k16.row.col.f16.f16.f16.f16 "
                 "{%0,%1}, {%2,%3,%4,%5}, {%6,%7}, {%0,%1};"
                 : "+r"(c[0]), "+r"(c[1])
                 : "r"(a[0]), "r"(a[1]), "r"(a[2]), "r"(a[3]), "r"(b0), "r"(b1));
}

// warp-cooperative top-64 (2 register slots per lane)
__device__ __forceinline__ void ins64(float& s0, float& s1, int& i0, int& i1,
                                      float& mx, float fv, int id, int lane) {
    const unsigned FULL = 0xffffffffu;
    for (;;) {
        unsigned m = __ballot_sync(FULL, fv < mx);
        if (!m) break;
        int src = __ffs(m) - 1;
        float ff = __shfl_sync(FULL, fv, src);
        int ii = __shfl_sync(FULL, id, src);
        float lm = fmaxf(s0, s1);
        float M = lm;
#pragma unroll
        for (int o = 16; o; o >>= 1) M = fmaxf(M, __shfl_xor_sync(FULL, M, o));
        unsigned hm = __ballot_sync(FULL, lm == M);
        int hl = __ffs(hm) - 1;
        if (lane == hl) {
            if (s0 >= s1) { s0 = ff; i0 = ii; }
            else          { s1 = ff; i1 = ii; }
        }
        lm = fmaxf(s0, s1);
#pragma unroll
        for (int o = 16; o; o >>= 1) lm = fmaxf(lm, __shfl_xor_sync(FULL, lm, o));
        mx = lm;
        if (lane == src) fv = F_INF;
    }
}

// ---------------- fused key conversion + k2 (one pass over mem_keys) -------
__global__ void cvtk2_kernel(const float* __restrict__ keys, __half* __restrict__ out,
                             float* __restrict__ k2) {
    int w = (blockIdx.x * blockDim.x + threadIdx.x) >> 5;
    int lane = threadIdx.x & 31;
    float4 v = *(const float4*)(keys + (size_t)w * ND + lane * 4);
    float s = v.x * v.x + v.y * v.y + v.z * v.z + v.w * v.w;
    s = warp_allred(s);
    if (lane == 0) k2[w] = s;
    __half2 a = __floats2half2_rn(v.x, v.y);
    __half2 b = __floats2half2_rn(v.z, v.w);
    uint2 o;
    o.x = *(uint32_t*)&a;
    o.y = *(uint32_t*)&b;
    *(uint2*)(out + (size_t)w * ND + lane * 4) = o;
}

// ---------------- z-batched encoder GEMM (two problems per launch) ---------
__global__ void gemmz_kernel(const float* __restrict__ A0, const float* __restrict__ A1,
                             const float* __restrict__ W0, const float* __restrict__ W1b,
                             const float* __restrict__ b0, const float* __restrict__ b1b,
                             float* __restrict__ C0, float* __restrict__ C1,
                             int relu_mask, int Md, int Nd, int Kd) {
    const int z = blockIdx.z;
    const float* A = z ? A1 : A0;
    const float* W = z ? W1b : W0;
    const float* bias = z ? b1b : b0;
    float* C = z ? C1 : C0;
    const int relu = (relu_mask >> z) & 1;

    __shared__ float As[64][17];
    __shared__ float Bs[16][64];
    const int tid = threadIdx.x;
    const int tn = tid & 15, tm = tid >> 4;
    const int row0 = blockIdx.y << 6, col0 = blockIdx.x << 6;
    const int arow = tid >> 2, acol = (tid & 3) << 2;
    const int brow = tid >> 4, bcol = (tid & 15) << 2;
    float acc[4][4] = {};
    for (int k0 = 0; k0 < Kd; k0 += 16) {
        float4 av = *(const float4*)(A + (size_t)(row0 + arow) * Kd + k0 + acol);
        float4 bv = *(const float4*)(W + (size_t)(k0 + brow) * Nd + col0 + bcol);
        As[arow][acol + 0] = av.x; As[arow][acol + 1] = av.y;
        As[arow][acol + 2] = av.z; As[arow][acol + 3] = av.w;
        *(float4*)&Bs[brow][bcol] = bv;
        __syncthreads();
#pragma unroll
        for (int kk = 0; kk < 16; ++kk) {
            float aa[4];
#pragma unroll
            for (int i = 0; i < 4; ++i) aa[i] = As[tm * 4 + i][kk];
            float4 b4 = *(float4*)&Bs[kk][tn * 4];
            float bb[4] = {b4.x, b4.y, b4.z, b4.w};
#pragma unroll
            for (int i = 0; i < 4; ++i)
#pragma unroll
                for (int j = 0; j < 4; ++j)
                    acc[i][j] = fmaf(aa[i], bb[j], acc[i][j]);
        }
        __syncthreads();
    }
    float4 bz = *(const float4*)(bias + col0 + tn * 4);
    float bb[4] = {bz.x, bz.y, bz.z, bz.w};
#pragma unroll
    for (int i = 0; i < 4; ++i) {
        float v0 = acc[i][0] + bb[0], v1 = acc[i][1] + bb[1];
        float v2 = acc[i][2] + bb[2], v3 = acc[i][3] + bb[3];
        if (relu) {
            v0 = fmaxf(v0, 0.f); v1 = fmaxf(v1, 0.f);
            v2 = fmaxf(v2, 0.f); v3 = fmaxf(v3, 0.f);
        }
        float4 o; o.x = v0; o.y = v1; o.z = v2; o.w = v3;
        *(float4*)(C + (size_t)(row0 + tm * 4 + i) * Nd + col0 + tn * 4) = o;
    }
}

__global__ void ln_kernel(const float* __restrict__ x, const float* __restrict__ g,
                          const float* __restrict__ b, float* __restrict__ q,
                          float* __restrict__ q2) {
    int row = (blockIdx.x * blockDim.x + threadIdx.x) >> 5;
    int lane = threadIdx.x & 31;
    float4 v = *(const float4*)(x + (size_t)row * ND + lane * 4);
    float mu = warp_allred(v.x + v.y + v.z + v.w) * (1.f / 128.f);
    float d0 = v.x - mu, d1 = v.y - mu, d2 = v.z - mu, d3 = v.w - mu;
    float var = warp_allred(d0 * d0 + d1 * d1 + d2 * d2 + d3 * d3) * (1.f / 128.f);
    float inv = rsqrtf(var + 1e-5f);
    float4 gg = *(const float4*)(g + lane * 4);
    float4 bb = *(const float4*)(b + lane * 4);
    float4 o;
    o.x = d0 * inv * gg.x + bb.x;
    o.y = d1 * inv * gg.y + bb.y;
    o.z = d2 * inv * gg.z + bb.z;
    o.w = d3 * inv * gg.w + bb.w;
    *(float4*)(q + (size_t)row * ND + lane * 4) = o;
    float qq = warp_allred(o.x * o.x + o.y * o.y + o.z * o.z + o.w * o.w);
    if (lane == 0) q2[row] = qq;
}

__global__ void net_kernel(const float* __restrict__ v2, const float* __restrict__ V3,
                           const float* __restrict__ c3, float* __restrict__ net) {
    int row = (blockIdx.x * blockDim.x + threadIdx.x) >> 5;
    int lane = threadIdx.x & 31;
    float4 a = *(const float4*)(v2 + (size_t)row * ND + lane * 4);
    float4 w = *(const float4*)(V3 + lane * 4);
    float s = warp_allred(a.x * w.x + a.y * w.y + a.z * w.z + a.w * w.w);
    if (lane == 0) net[row] = s + c3[0];
}

// ---------------- phase 1: fp16 mma GEMM -> fp16 scores + block minima ----
#define SM_B    0        // 2 x 32768: key tiles, swizzled (row*256 + (u^(row&7))*16)
#define SM_QS   65536    // 32768: q fp16 staging
#define SM_K2   98304    // 2 x 512
#define SM_TOT  99328

__device__ __forceinline__ void p1_load_tile(int t, int m0s, int tid, uint32_t sb,
                                             float* k2s, const __half* keysh,
                                             const float* k2g) {
    const int buf = t & 1;
    const int m0t = m0s + t * TILEN;
#pragma unroll
    for (int it = 0; it < 4; ++it) {
        int idx = tid + (it << 9);
        int row = idx >> 4, u = idx & 15;
        int gm = m0t + row;
        if (gm < NM)
            cp16(sb + SM_B + buf * 32768 + row * 256 + ((u ^ (row & 7)) << 4),
                 keysh + (size_t)gm * ND + u * 8);
    }
    if (tid < 32) {
        int g0 = m0t + tid * 4;
        if (g0 + 3 < NM) {
            cp16(sb + SM_K2 + buf * 512 + (tid << 4), k2g + g0);
        } else {
#pragma unroll
            for (int u2 = 0; u2 < 4; ++u2) {
                int g = g0 + u2;
                k2s[buf * 128 + tid * 4 + u2] = (g < NM) ? __ldg(k2g + g) : F_INF;
            }
        }
    }
    asm volatile("cp.async.commit_group;\n" ::: "memory");
}

__global__ void __launch_bounds__(512, 1)
p1_kernel(const float* __restrict__ q, const __half* __restrict__ keysh,
          const float* __restrict__ k2g, __half* __restrict__ dist,
          __half* __restrict__ tmin) {
    extern __shared__ __align__(16) char sm[];
    const uint32_t sb = smem_u32(sm);
    float* k2s = (float*)(sm + SM_K2);
    const unsigned FULL = 0xffffffffu;

    const int tid = threadIdx.x;
    const int w = tid >> 5;
    const int lt = tid & 31;
    const int wr = w & 7;          // q-row group
    const int wh = w >> 3;         // key half (0/1)
    const int s = blockIdx.x, qb = blockIdx.y;
    const int m0s = s * SPLEN;
    const int mlen = min(SPLEN, NM - m0s);
    const int T = (mlen + TILEN - 1) / TILEN;

    // stage q block as fp16 (swizzled)
#pragma unroll
    for (int it = 0; it < 4; ++it) {
        int idx = tid + (it << 9);
        int row = idx >> 4, u = idx & 15;
        const float* src = q + (size_t)(qb * 128 + row) * ND + u * 8;
        float4 v0 = *(const float4*)src;
        float4 v1 = *(const float4*)(src + 4);
        __half2 p0 = __floats2half2_rn(v0.x, v0.y);
        __half2 p1 = __floats2half2_rn(v0.z, v0.w);
        __half2 p2 = __floats2half2_rn(v1.x, v1.y);
        __half2 p3 = __floats2half2_rn(v1.z, v1.w);
        uint4 pk;
        pk.x = *(uint32_t*)&p0; pk.y = *(uint32_t*)&p1;
        pk.z = *(uint32_t*)&p2; pk.w = *(uint32_t*)&p3;
        *(uint4*)(sm + SM_QS + row * 256 + ((u ^ (row & 7)) << 4)) = pk;
    }
    __syncthreads();

    // persistent A fragments (warp covers q rows [wr*16, wr*16+16))
    uint32_t af[8][4];
    {
        int mrow = wr * 16 + (lt & 7) + ((lt >> 3) & 1) * 8;
        int kh = lt >> 4;
        uint32_t abase = sb + SM_QS + mrow * 256;
        int msw = mrow & 7;
#pragma unroll
        for (int kk = 0; kk < 8; ++kk)
            ldsm_x4(af[kk][0], af[kk][1], af[kk][2], af[kk][3],
                    abase + ((((kk << 1) | kh) ^ msw) << 4));
    }

    p1_load_tile(0, m0s, tid, sb, k2s, keysh, k2g);

    const int nbase = (lt >> 4) * 8 + (lt & 7);
    const int hh = (lt >> 3) & 1;
    const int r0 = wr * 16 + (lt >> 2);
    const int cbase = (lt & 3) << 1;
    __half* drow0 = dist + (size_t)(qb * 128 + r0) * NM;
    __half* drow1 = drow0 + (size_t)8 * NM;

    for (int t = 0; t < T; ++t) {
        const int buf = t & 1;
        asm volatile("cp.async.wait_group 0;\n" ::: "memory");
        __syncthreads();
        if (t + 1 < T) p1_load_tile(t + 1, m0s, tid, sb, k2s, keysh, k2g);

        // fp16 accumulators: 8 n-tiles x 2 packed regs
        uint32_t acc[8][2];
#pragma unroll
        for (int j = 0; j < 8; ++j) { acc[j][0] = 0; acc[j][1] = 0; }

        const uint32_t bbase = sb + SM_B + buf * 32768 + wh * 16384;
#pragma unroll
        for (int kk = 0; kk < 8; ++kk) {
#pragma unroll
            for (int jp = 0; jp < 4; ++jp) {
                int n = jp * 16 + nbase;
                uint32_t addr = bbase + n * 256 + ((((kk << 1) | hh) ^ (n & 7)) << 4);
                uint32_t b0, b1, b2, b3;
                ldsm_x4(b0, b1, b2, b3, addr);
                mma_f16acc(acc[2 * jp], af[kk], b0, b1);
                mma_f16acc(acc[2 * jp + 1], af[kk], b2, b3);
            }
        }

        // stream scores (k2 - 2*dot) to HBM as fp16, tracking block minima
        const int m0t = m0s + t * TILEN;
        float mn0 = F_INF, mn1 = F_INF;
#pragma unroll
        for (int j = 0; j < 8; ++j) {
            int c = wh * 64 + j * 8 + cbase;
            int gc = m0t + c;
            if (gc < NM) {
                float2 kk2 = *(float2*)(k2s + buf * 128 + c);
                float2 lo = __half22float2(*(__half2*)&acc[j][0]);   // row r0
                float2 hi = __half22float2(*(__half2*)&acc[j][1]);   // row r0+8
                float2 s0, s1;
                s0.x = fmaf(lo.x, -2.f, kk2.x);
                s0.y = fmaf(lo.y, -2.f, kk2.y);
                s1.x = fmaf(hi.x, -2.f, kk2.x);
                s1.y = fmaf(hi.y, -2.f, kk2.y);
                mn0 = fminf(mn0, fminf(s0.x, s0.y));
                mn1 = fminf(mn1, fminf(s1.x, s1.y));
                *(__half2*)(drow0 + gc) = __float22half2_rn(s0);
                *(__half2*)(drow1 + gc) = __float22half2_rn(s1);
            }
        }
        // reduce mins across the lane quad
        mn0 = fminf(mn0, __shfl_xor_sync(FULL, mn0, 1));
        mn0 = fminf(mn0, __shfl_xor_sync(FULL, mn0, 2));
        mn1 = fminf(mn1, __shfl_xor_sync(FULL, mn1, 1));
        mn1 = fminf(mn1, __shfl_xor_sync(FULL, mn1, 2));
        if ((lt & 3) == 0) {
            size_t base = (size_t)(qb * 128 + r0) * NBLK + s * 196 + t * 2 + wh;
            tmin[base] = __float2half(mn0);
            tmin[base + (size_t)8 * NBLK] = __float2half(mn1);
        }
    }
}

// ---------------- selection: block-min prune + exact top-64 ---------------
__global__ void __launch_bounds__(256)
sel_kernel(const __half* __restrict__ dist, const __half* __restrict__ tmin,
           int* __restrict__ cand) {
    const unsigned FULL = 0xffffffffu;
    __shared__ int bids_s[8][64];
    const int wrp = threadIdx.x >> 5;
    const int wid = (blockIdx.x * blockDim.x + threadIdx.x) >> 5;  // row 0..4095
    const int lane = threadIdx.x & 31;

    // ---- pass A: top-64 of block minima -> candidate block ids ----
    float s0 = F_INF, s1 = F_INF;
    int i0 = 0, i1 = 0;
    float mx = F_INF;
    const __half* trow = tmin + (size_t)wid * NBLK;
    for (int i = 0; i < 25; ++i) {
        int idx = i * 32 + lane;
        float fv = F_INF;
        if (idx < NBLK) {
            int key0 = (idx / 196) * SPLEN + (idx % 196) * 64;
            if (key0 < NM) fv = __half2float(trow[idx]);
        }
        if (__ballot_sync(FULL, fv < mx))
            ins64(s0, s1, i0, i1, mx, fv, idx, lane);
    }
    bids_s[wrp][lane * 2] = i0;
    bids_s[wrp][lane * 2 + 1] = i1;
    __syncwarp();

    // ---- pass B: exact top-64 over the 64 candidate blocks ----
    s0 = F_INF; s1 = F_INF; i0 = 0; i1 = 0; mx = F_INF;
    const __half* row = dist + (size_t)wid * NM;
    for (int b = 0; b < 64; ++b) {
        int bid = bids_s[wrp][b];
        int key0 = (bid / 196) * SPLEN + (bid % 196) * 64;
        int key = key0 + lane * 2;
        float f0 = F_INF, f1 = F_INF;
        if (key < NM) {
            float2 ff = __half22float2(*(const __half2*)(row + key));
            f0 = ff.x; f1 = ff.y;
        }
        if (__ballot_sync(FULL, fminf(f0, f1) < mx)) {
            ins64(s0, s1, i0, i1, mx, f0, key, lane);
            ins64(s0, s1, i0, i1, mx, f1, key + 1, lane);
        }
    }
    int* dst = cand + (size_t)wid * 64;
    dst[lane * 2] = i0;
    dst[lane * 2 + 1] = i1;
}

// ---------------- phase 2: exact fp32 rescore + top-50 + output ------------
__global__ void __launch_bounds__(64)
p2_kernel(const float* __restrict__ q, const float* __restrict__ q2g,
          const float* __restrict__ k2g, const float* __restrict__ keys,
          const float* __restrict__ vals, const float* __restrict__ net,
          const int* __restrict__ cand, float* __restrict__ out) {
    __shared__ float qs[128];
    __shared__ float ds[64];
    __shared__ int isx[64];
    __shared__ float part[4];
    const int row = blockIdx.x;
    const int tid = threadIdx.x;
    qs[tid] = q[(size_t)row * ND + tid];
    qs[tid + 64] = q[(size_t)row * ND + tid + 64];
    __syncthreads();

    int c = cand[(size_t)row * 64 + tid];
    const float4* kr = (const float4*)(keys + (size_t)c * ND);
    float dot = 0.f;
#pragma unroll 8
    for (int i = 0; i < 32; ++i) {
        float4 k4 = kr[i];
        float4 q4 = *(const float4*)(qs + i * 4);
        dot = fmaf(k4.x, q4.x, dot);
        dot = fmaf(k4.y, q4.y, dot);
        dot = fmaf(k4.z, q4.z, dot);
        dot = fmaf(k4.w, q4.w, dot);
    }
    ds[tid] = q2g[row] + k2g[c] - 2.f * dot;
    isx[tid] = c;
    __syncthreads();

    // bitonic sort 64 by (dist, idx) ascending
    for (int k = 2; k <= 64; k <<= 1) {
        for (int j = k >> 1; j > 0; j >>= 1) {
            int p = tid ^ j;
            if (p > tid) {
                float d1 = ds[tid], d2 = ds[p];
                int i1 = isx[tid], i2 = isx[p];
                bool up = (tid & k) == 0;
                bool gt = (d1 > d2) || (d1 == d2 && i1 > i2);
                if (up ? gt : !gt) {
                    ds[tid] = d2; ds[p] = d1;
                    isx[tid] = i2; isx[p] = i1;
                }
            }
            __syncthreads();
        }
    }

    float wgt = 0.f, wv = 0.f;
    if (tid < NK) {
        wgt = 1.f / (ds[tid] + 1e-7f);
        wv = wgt * vals[isx[tid]];
    }
    float ws = warp_allred(wgt), vs = warp_allred(wv);
    if ((tid & 31) == 0) { part[tid >> 5] = ws; part[2 + (tid >> 5)] = vs; }
    __syncthreads();
    if (tid == 0) {
        float W = part[0] + part[1], V = part[2] + part[3];
        out[row] = 0.9f * (V / W) + 0.1f * net[row];
    }
}

// ---------------- launch ----------------
extern "C" void kernel_launch(void* const* d_in, const int* in_sizes, int n_in,
                              void* d_out, int out_size) {
    const float* states     = (const float*)d_in[0];
    const float* W1         = (const float*)d_in[1];
    const float* b1         = (const float*)d_in[2];
    const float* W2         = (const float*)d_in[3];
    const float* b2         = (const float*)d_in[4];
    const float* ln_g       = (const float*)d_in[5];
    const float* ln_b       = (const float*)d_in[6];
    const float* mem_keys   = (const float*)d_in[7];
    const float* mem_values = (const float*)d_in[8];
    const float* V1         = (const float*)d_in[9];
    const float* c1         = (const float*)d_in[10];
    const float* V2         = (const float*)d_in[11];
    const float* c2         = (const float*)d_in[12];
    const float* V3         = (const float*)d_in[13];
    const float* c3         = (const float*)d_in[14];
    float* out = (float*)d_out;

    void *ph, *pqpre, *pq, *pq2, *pk2, *pv1, *pv2, *pnet, *pkh, *pdist, *ptmin, *pcand;
    cudaGetSymbolAddress(&ph, g_h);
    cudaGetSymbolAddress(&pqpre, g_qpre);
    cudaGetSymbolAddress(&pq, g_q);
    cudaGetSymbolAddress(&pq2, g_q2);
    cudaGetSymbolAddress(&pk2, g_k2);
    cudaGetSymbolAddress(&pv1, g_v1);
    cudaGetSymbolAddress(&pv2, g_v2);
    cudaGetSymbolAddress(&pnet, g_net);
    cudaGetSymbolAddress(&pkh, g_keysh);
    cudaGetSymbolAddress(&pdist, g_dist);
    cudaGetSymbolAddress(&ptmin, g_tmin);
    cudaGetSymbolAddress(&pcand, g_cand);

    cudaFuncSetAttribute(p1_kernel, cudaFuncAttributeMaxDynamicSharedMemorySize, SM_TOT);

    cvtk2_kernel<<<NM / 8, 256>>>(mem_keys, (__half*)pkh, (float*)pk2);                  // 1

    gemmz_kernel<<<dim3(NH / 64, NB / 64, 2), 256>>>(states, states, W1, V1, b1, c1,
                                                     (float*)ph, (float*)pv1, 3,
                                                     NB, NH, NS);                        // 2
    gemmz_kernel<<<dim3(ND / 64, NB / 64, 2), 256>>>((const float*)ph, (const float*)pv1,
                                                     W2, V2, b2, c2,
                                                     (float*)pqpre, (float*)pv2, 2,
                                                     NB, ND, NH);                        // 3

    ln_kernel<<<NB / 8, 256>>>((const float*)pqpre, ln_g, ln_b, (float*)pq, (float*)pq2);// 4
    net_kernel<<<NB / 8, 256>>>((const float*)pv2, V3, c3, (float*)pnet);                // 5

    p1_kernel<<<dim3(NSPLIT, NB / 128), 512, SM_TOT>>>((const float*)pq,                 // 6
                                                       (const __half*)pkh,
                                                       (const float*)pk2,
                                                       (__half*)pdist, (__half*)ptmin);

    sel_kernel<<<NB / 8, 256>>>((const __half*)pdist, (const __half*)ptmin, (int*)pcand);// 7

    p2_kernel<<<NB, 64>>>((const float*)pq, (const float*)pq2, (const float*)pk2,
                          mem_keys, mem_values, (const float*)pnet,
                          (const int*)pcand, out);                                       // 8
}

// round 15
// speedup vs baseline: 1.0342x; 1.0342x over previous
#include <cuda_runtime.h>
#include <cuda_bf16.h>
#include <cuda_fp16.h>
#include <cstdint>
#include <cstddef>

#define NB 4096
#define NS 544
#define NH 256
#define ND 128
#define NM 50000
#define NK 50
#define NSPLIT 4
#define SPLEN 12544      // 98 * 128
#define TILEN 128
#define NBLK 784         // 4 splits * 196 blocks of 64 keys
#define F_INF __int_as_float(0x7f800000)

// ---------------- scratch (static device globals; no allocations) ----------
__device__ float g_h[NB * NH];
__device__ float g_qpre[NB * ND];
__device__ float g_q[NB * ND];
__device__ float g_q2[NB];
__device__ float g_k2[NM];
__device__ float g_v1[NB * NH];
__device__ float g_v2[NB * ND];
__device__ float g_net[NB];
__device__ __nv_bfloat16 g_keys16[NM * ND];
__device__ __half g_dist[(size_t)NB * NM];     // 409.6 MB fp16 score matrix
__device__ __half g_tmin[(size_t)NB * NBLK];   // 6.4 MB block minima
__device__ int g_cand[NB * 64];

// ---------------- helpers ----------------
__device__ __forceinline__ uint32_t smem_u32(const void* p) {
    uint32_t a;
    asm("{ .reg .u64 t; cvta.to.shared.u64 t, %1; cvt.u32.u64 %0, t; }" : "=r"(a) : "l"(p));
    return a;
}
__device__ __forceinline__ void cp16(uint32_t dst, const void* src) {
    asm volatile("cp.async.ca.shared.global [%0], [%1], 16;\n" :: "r"(dst), "l"(src));
}
__device__ __forceinline__ float warp_allred(float v) {
#pragma unroll
    for (int o = 16; o; o >>= 1) v += __shfl_xor_sync(0xffffffffu, v, o);
    return v;
}
__device__ __forceinline__ void ldsm_x4(uint32_t& r0, uint32_t& r1, uint32_t& r2,
                                        uint32_t& r3, uint32_t addr) {
    asm volatile("ldmatrix.sync.aligned.m8n8.x4.shared.b16 {%0,%1,%2,%3}, [%4];"
                 : "=r"(r0), "=r"(r1), "=r"(r2), "=r"(r3) : "r"(addr));
}
__device__ __forceinline__ void mma_bf16(float* c, const uint32_t* a, uint32_t b0, uint32_t b1) {
    asm volatile("mma.sync.aligned.m16n8k16.row.col.f32.bf16.bf16.f32 "
                 "{%0,%1,%2,%3}, {%4,%5,%6,%7}, {%8,%9}, {%0,%1,%2,%3};"
                 : "+f"(c[0]), "+f"(c[1]), "+f"(c[2]), "+f"(c[3])
                 : "r"(a[0]), "r"(a[1]), "r"(a[2]), "r"(a[3]), "r"(b0), "r"(b1));
}

// warp-cooperative top-64 (2 register slots per lane)
__device__ __forceinline__ void ins64(float& s0, float& s1, int& i0, int& i1,
                                      float& mx, float fv, int id, int lane) {
    const unsigned FULL = 0xffffffffu;
    for (;;) {
        unsigned m = __ballot_sync(FULL, fv < mx);
        if (!m) break;
        int src = __ffs(m) - 1;
        float ff = __shfl_sync(FULL, fv, src);
        int ii = __shfl_sync(FULL, id, src);
        float lm = fmaxf(s0, s1);
        float M = lm;
#pragma unroll
        for (int o = 16; o; o >>= 1) M = fmaxf(M, __shfl_xor_sync(FULL, M, o));
        unsigned hm = __ballot_sync(FULL, lm == M);
        int hl = __ffs(hm) - 1;
        if (lane == hl) {
            if (s0 >= s1) { s0 = ff; i0 = ii; }
            else          { s1 = ff; i1 = ii; }
        }
        lm = fmaxf(s0, s1);
#pragma unroll
        for (int o = 16; o; o >>= 1) lm = fmaxf(lm, __shfl_xor_sync(FULL, lm, o));
        mx = lm;
        if (lane == src) fv = F_INF;
    }
}

// ---------------- fused key conversion + k2 (one pass over mem_keys) -------
__global__ void cvtk2_kernel(const float* __restrict__ keys, __nv_bfloat16* __restrict__ out,
                             float* __restrict__ k2) {
    int w = (blockIdx.x * blockDim.x + threadIdx.x) >> 5;
    int lane = threadIdx.x & 31;
    float4 v = *(const float4*)(keys + (size_t)w * ND + lane * 4);
    float s = v.x * v.x + v.y * v.y + v.z * v.z + v.w * v.w;
    s = warp_allred(s);
    if (lane == 0) k2[w] = s;
    __nv_bfloat162 a = __floats2bfloat162_rn(v.x, v.y);
    __nv_bfloat162 b = __floats2bfloat162_rn(v.z, v.w);
    uint2 o;
    o.x = *(uint32_t*)&a;
    o.y = *(uint32_t*)&b;
    *(uint2*)(out + (size_t)w * ND + lane * 4) = o;
}

// ---------------- z-batched encoder GEMM, cp.async double-buffered ---------
// As stride = 20 floats (80 B): keeps every cp.async dst 16 B-aligned.
__global__ void gemmz_kernel(const float* __restrict__ A0, const float* __restrict__ A1,
                             const float* __restrict__ W0, const float* __restrict__ W1b,
                             const float* __restrict__ b0, const float* __restrict__ b1b,
                             float* __restrict__ C0, float* __restrict__ C1,
                             int relu_mask, int Md, int Nd, int Kd) {
    const int z = blockIdx.z;
    const float* A = z ? A1 : A0;
    const float* W = z ? W1b : W0;
    const float* bias = z ? b1b : b0;
    float* C = z ? C1 : C0;
    const int relu = (relu_mask >> z) & 1;

    __shared__ __align__(16) float As[2][64][20];
    __shared__ __align__(16) float Bs[2][16][64];
    const int tid = threadIdx.x;
    const int tn = tid & 15, tm = tid >> 4;
    const int row0 = blockIdx.y << 6, col0 = blockIdx.x << 6;
    const int arow = tid >> 2, acol = (tid & 3) << 2;
    const int brow = tid >> 4, bcol = (tid & 15) << 2;
    const int NSTG = Kd >> 4;

    const uint32_t sa = smem_u32(&As[0][0][0]);
    const uint32_t sbs = smem_u32(&Bs[0][0][0]);

    // prefetch stage 0
    cp16(sa + (arow * 20 + acol) * 4, A + (size_t)(row0 + arow) * Kd + acol);
    cp16(sbs + (brow * 64 + bcol) * 4, W + (size_t)brow * Nd + col0 + bcol);
    asm volatile("cp.async.commit_group;\n" ::: "memory");

    float acc[4][4] = {};
    for (int st = 0; st < NSTG; ++st) {
        const int buf = st & 1;
        if (st + 1 < NSTG) {
            const int nb = (st + 1) & 1;
            const int k0 = (st + 1) << 4;
            cp16(sa + (nb * 64 * 20 + arow * 20 + acol) * 4,
                 A + (size_t)(row0 + arow) * Kd + k0 + acol);
            cp16(sbs + (nb * 16 * 64 + brow * 64 + bcol) * 4,
                 W + (size_t)(k0 + brow) * Nd + col0 + bcol);
            asm volatile("cp.async.commit_group;\n" ::: "memory");
            asm volatile("cp.async.wait_group 1;\n" ::: "memory");
        } else {
            asm volatile("cp.async.wait_group 0;\n" ::: "memory");
        }
        __syncthreads();
#pragma unroll
        for (int kk = 0; kk < 16; ++kk) {
            float aa[4];
#pragma unroll
            for (int i = 0; i < 4; ++i) aa[i] = As[buf][tm * 4 + i][kk];
            float4 b4 = *(float4*)&Bs[buf][kk][tn * 4];
            float bb[4] = {b4.x, b4.y, b4.z, b4.w};
#pragma unroll
            for (int i = 0; i < 4; ++i)
#pragma unroll
                for (int j = 0; j < 4; ++j)
                    acc[i][j] = fmaf(aa[i], bb[j], acc[i][j]);
        }
        __syncthreads();
    }
    float4 bz = *(const float4*)(bias + col0 + tn * 4);
    float bb[4] = {bz.x, bz.y, bz.z, bz.w};
#pragma unroll
    for (int i = 0; i < 4; ++i) {
        float v0 = acc[i][0] + bb[0], v1 = acc[i][1] + bb[1];
        float v2 = acc[i][2] + bb[2], v3 = acc[i][3] + bb[3];
        if (relu) {
            v0 = fmaxf(v0, 0.f); v1 = fmaxf(v1, 0.f);
            v2 = fmaxf(v2, 0.f); v3 = fmaxf(v3, 0.f);
        }
        float4 o; o.x = v0; o.y = v1; o.z = v2; o.w = v3;
        *(float4*)(C + (size_t)(row0 + tm * 4 + i) * Nd + col0 + tn * 4) = o;
    }
}

__global__ void ln_kernel(const float* __restrict__ x, const float* __restrict__ g,
                          const float* __restrict__ b, float* __restrict__ q,
                          float* __restrict__ q2) {
    int row = (blockIdx.x * blockDim.x + threadIdx.x) >> 5;
    int lane = threadIdx.x & 31;
    float4 v = *(const float4*)(x + (size_t)row * ND + lane * 4);
    float mu = warp_allred(v.x + v.y + v.z + v.w) * (1.f / 128.f);
    float d0 = v.x - mu, d1 = v.y - mu, d2 = v.z - mu, d3 = v.w - mu;
    float var = warp_allred(d0 * d0 + d1 * d1 + d2 * d2 + d3 * d3) * (1.f / 128.f);
    float inv = rsqrtf(var + 1e-5f);
    float4 gg = *(const float4*)(g + lane * 4);
    float4 bb = *(const float4*)(b + lane * 4);
    float4 o;
    o.x = d0 * inv * gg.x + bb.x;
    o.y = d1 * inv * gg.y + bb.y;
    o.z = d2 * inv * gg.z + bb.z;
    o.w = d3 * inv * gg.w + bb.w;
    *(float4*)(q + (size_t)row * ND + lane * 4) = o;
    float qq = warp_allred(o.x * o.x + o.y * o.y + o.z * o.z + o.w * o.w);
    if (lane == 0) q2[row] = qq;
}

__global__ void net_kernel(const float* __restrict__ v2, const float* __restrict__ V3,
                           const float* __restrict__ c3, float* __restrict__ net) {
    int row = (blockIdx.x * blockDim.x + threadIdx.x) >> 5;
    int lane = threadIdx.x & 31;
    float4 a = *(const float4*)(v2 + (size_t)row * ND + lane * 4);
    float4 w = *(const float4*)(V3 + lane * 4);
    float s = warp_allred(a.x * w.x + a.y * w.y + a.z * w.z + a.w * w.w);
    if (lane == 0) net[row] = s + c3[0];
}

// ---------------- phase 1: bf16 mma GEMM -> fp16 scores + block minima ----
#define SM_B    0        // 2 x 32768: key tiles, swizzled (row*256 + (u^(row&7))*16)
#define SM_QS   65536    // 32768: q bf16 staging
#define SM_K2   98304    // 2 x 512
#define SM_TOT  99328

__device__ __forceinline__ void p1_load_tile(int t, int m0s, int tid, uint32_t sb,
                                             float* k2s, const __nv_bfloat16* keys16,
                                             const float* k2g) {
    const int buf = t & 1;
    const int m0t = m0s + t * TILEN;
#pragma unroll
    for (int it = 0; it < 4; ++it) {
        int idx = tid + (it << 9);
        int row = idx >> 4, u = idx & 15;
        int gm = m0t + row;
        if (gm < NM)
            cp16(sb + SM_B + buf * 32768 + row * 256 + ((u ^ (row & 7)) << 4),
                 keys16 + (size_t)gm * ND + u * 8);
    }
    if (tid < 32) {
        int g0 = m0t + tid * 4;
        if (g0 + 3 < NM) {
            cp16(sb + SM_K2 + buf * 512 + (tid << 4), k2g + g0);
        } else {
#pragma unroll
            for (int u2 = 0; u2 < 4; ++u2) {
                int g = g0 + u2;
                k2s[buf * 128 + tid * 4 + u2] = (g < NM) ? __ldg(k2g + g) : F_INF;
            }
        }
    }
    asm volatile("cp.async.commit_group;\n" ::: "memory");
}

__global__ void __launch_bounds__(512, 1)
p1_kernel(const float* __restrict__ q, const __nv_bfloat16* __restrict__ keys16,
          const float* __restrict__ k2g, __half* __restrict__ dist,
          __half* __restrict__ tmin) {
    extern __shared__ __align__(16) char sm[];
    const uint32_t sb = smem_u32(sm);
    float* k2s = (float*)(sm + SM_K2);
    const unsigned FULL = 0xffffffffu;

    const int tid = threadIdx.x;
    const int w = tid >> 5;
    const int lt = tid & 31;
    const int wr = w & 7;          // q-row group
    const int wh = w >> 3;         // key half (0/1)
    const int s = blockIdx.x, qb = blockIdx.y;
    const int m0s = s * SPLEN;
    const int mlen = min(SPLEN, NM - m0s);
    const int T = (mlen + TILEN - 1) / TILEN;

    // stage q block as bf16 (swizzled)
#pragma unroll
    for (int it = 0; it < 4; ++it) {
        int idx = tid + (it << 9);
        int row = idx >> 4, u = idx & 15;
        const float* src = q + (size_t)(qb * 128 + row) * ND + u * 8;
        float4 v0 = *(const float4*)src;
        float4 v1 = *(const float4*)(src + 4);
        __nv_bfloat162 p0 = __floats2bfloat162_rn(v0.x, v0.y);
        __nv_bfloat162 p1 = __floats2bfloat162_rn(v0.z, v0.w);
        __nv_bfloat162 p2 = __floats2bfloat162_rn(v1.x, v1.y);
        __nv_bfloat162 p3 = __floats2bfloat162_rn(v1.z, v1.w);
        uint4 pk;
        pk.x = *(uint32_t*)&p0; pk.y = *(uint32_t*)&p1;
        pk.z = *(uint32_t*)&p2; pk.w = *(uint32_t*)&p3;
        *(uint4*)(sm + SM_QS + row * 256 + ((u ^ (row & 7)) << 4)) = pk;
    }
    __syncthreads();

    // persistent A fragments (warp covers q rows [wr*16, wr*16+16))
    uint32_t af[8][4];
    {
        int mrow = wr * 16 + (lt & 7) + ((lt >> 3) & 1) * 8;
        int kh = lt >> 4;
        uint32_t abase = sb + SM_QS + mrow * 256;
        int msw = mrow & 7;
#pragma unroll
        for (int kk = 0; kk < 8; ++kk)
            ldsm_x4(af[kk][0], af[kk][1], af[kk][2], af[kk][3],
                    abase + ((((kk << 1) | kh) ^ msw) << 4));
    }

    p1_load_tile(0, m0s, tid, sb, k2s, keys16, k2g);

    const int nbase = (lt >> 4) * 8 + (lt & 7);
    const int hh = (lt >> 3) & 1;
    const int r0 = wr * 16 + (lt >> 2);
    const int cbase = (lt & 3) << 1;
    __half* drow0 = dist + (size_t)(qb * 128 + r0) * NM;
    __half* drow1 = drow0 + (size_t)8 * NM;

    for (int t = 0; t < T; ++t) {
        const int buf = t & 1;
        asm volatile("cp.async.wait_group 0;\n" ::: "memory");
        __syncthreads();
        if (t + 1 < T) p1_load_tile(t + 1, m0s, tid, sb, k2s, keys16, k2g);

        float acc[8][4];
#pragma unroll
        for (int j = 0; j < 8; ++j)
#pragma unroll
            for (int e = 0; e < 4; ++e) acc[j][e] = 0.f;

        const uint32_t bbase = sb + SM_B + buf * 32768 + wh * 16384;
#pragma unroll
        for (int kk = 0; kk < 8; ++kk) {
#pragma unroll
            for (int jp = 0; jp < 4; ++jp) {
                int n = jp * 16 + nbase;
                uint32_t addr = bbase + n * 256 + ((((kk << 1) | hh) ^ (n & 7)) << 4);
                uint32_t b0, b1, b2, b3;
                ldsm_x4(b0, b1, b2, b3, addr);
                mma_bf16(acc[2 * jp], af[kk], b0, b1);
                mma_bf16(acc[2 * jp + 1], af[kk], b2, b3);
            }
        }

        // stream scores (k2 - 2*dot) to HBM as fp16, tracking block minima
        const int m0t = m0s + t * TILEN;
        float mn0 = F_INF, mn1 = F_INF;
#pragma unroll
        for (int j = 0; j < 8; ++j) {
            int c = wh * 64 + j * 8 + cbase;
            int gc = m0t + c;
            if (gc < NM) {
                float2 kk2 = *(float2*)(k2s + buf * 128 + c);
                float2 s0, s1;
                s0.x = fmaf(acc[j][0], -2.f, kk2.x);
                s0.y = fmaf(acc[j][1], -2.f, kk2.y);
                s1.x = fmaf(acc[j][2], -2.f, kk2.x);
                s1.y = fmaf(acc[j][3], -2.f, kk2.y);
                mn0 = fminf(mn0, fminf(s0.x, s0.y));
                mn1 = fminf(mn1, fminf(s1.x, s1.y));
                *(__half2*)(drow0 + gc) = __float22half2_rn(s0);
                *(__half2*)(drow1 + gc) = __float22half2_rn(s1);
            }
        }
        // reduce mins across the lane quad
        mn0 = fminf(mn0, __shfl_xor_sync(FULL, mn0, 1));
        mn0 = fminf(mn0, __shfl_xor_sync(FULL, mn0, 2));
        mn1 = fminf(mn1, __shfl_xor_sync(FULL, mn1, 1));
        mn1 = fminf(mn1, __shfl_xor_sync(FULL, mn1, 2));
        if ((lt & 3) == 0) {
            size_t base = (size_t)(qb * 128 + r0) * NBLK + s * 196 + t * 2 + wh;
            tmin[base] = __float2half(mn0);
            tmin[base + (size_t)8 * NBLK] = __float2half(mn1);
        }
    }
}

// ---------------- selection: block-min prune + exact top-64 ---------------
__global__ void __launch_bounds__(256)
sel_kernel(const __half* __restrict__ dist, const __half* __restrict__ tmin,
           int* __restrict__ cand) {
    const unsigned FULL = 0xffffffffu;
    __shared__ int bids_s[8][64];
    const int wrp = threadIdx.x >> 5;
    const int wid = (blockIdx.x * blockDim.x + threadIdx.x) >> 5;  // row 0..4095
    const int lane = threadIdx.x & 31;

    // ---- pass A: top-64 of block minima -> candidate block ids ----
    float s0 = F_INF, s1 = F_INF;
    int i0 = 0, i1 = 0;
    float mx = F_INF;
    const __half* trow = tmin + (size_t)wid * NBLK;
    for (int i = 0; i < 25; ++i) {
        int idx = i * 32 + lane;
        float fv = F_INF;
        if (idx < NBLK) {
            int key0 = (idx / 196) * SPLEN + (idx % 196) * 64;
            if (key0 < NM) fv = __half2float(trow[idx]);
        }
        if (__ballot_sync(FULL, fv < mx))
            ins64(s0, s1, i0, i1, mx, fv, idx, lane);
    }
    bids_s[wrp][lane * 2] = i0;
    bids_s[wrp][lane * 2 + 1] = i1;
    __syncwarp();

    // ---- pass B: exact top-64 over the 64 candidate blocks ----
    s0 = F_INF; s1 = F_INF; i0 = 0; i1 = 0; mx = F_INF;
    const __half* row = dist + (size_t)wid * NM;
    for (int b = 0; b < 64; ++b) {
        int bid = bids_s[wrp][b];
        int key0 = (bid / 196) * SPLEN + (bid % 196) * 64;
        int key = key0 + lane * 2;
        float f0 = F_INF, f1 = F_INF;
        if (key < NM) {
            float2 ff = __half22float2(*(const __half2*)(row + key));
            f0 = ff.x; f1 = ff.y;
        }
        if (__ballot_sync(FULL, fminf(f0, f1) < mx)) {
            ins64(s0, s1, i0, i1, mx, f0, key, lane);
            ins64(s0, s1, i0, i1, mx, f1, key + 1, lane);
        }
    }
    int* dst = cand + (size_t)wid * 64;
    dst[lane * 2] = i0;
    dst[lane * 2 + 1] = i1;
}

// ---------------- phase 2: exact fp32 rescore + top-50 + output ------------
__global__ void __launch_bounds__(64)
p2_kernel(const float* __restrict__ q, const float* __restrict__ q2g,
          const float* __restrict__ k2g, const float* __restrict__ keys,
          const float* __restrict__ vals, const float* __restrict__ net,
          const int* __restrict__ cand, float* __restrict__ out) {
    __shared__ float qs[128];
    __shared__ float ds[64];
    __shared__ int isx[64];
    __shared__ float part[4];
    const int row = blockIdx.x;
    const int tid = threadIdx.x;
    qs[tid] = q[(size_t)row * ND + tid];
    qs[tid + 64] = q[(size_t)row * ND + tid + 64];
    __syncthreads();

    int c = cand[(size_t)row * 64 + tid];
    const float4* kr = (const float4*)(keys + (size_t)c * ND);
    float dot = 0.f;
#pragma unroll 8
    for (int i = 0; i < 32; ++i) {
        float4 k4 = kr[i];
        float4 q4 = *(const float4*)(qs + i * 4);
        dot = fmaf(k4.x, q4.x, dot);
        dot = fmaf(k4.y, q4.y, dot);
        dot = fmaf(k4.z, q4.z, dot);
        dot = fmaf(k4.w, q4.w, dot);
    }
    ds[tid] = q2g[row] + k2g[c] - 2.f * dot;
    isx[tid] = c;
    __syncthreads();

    // bitonic sort 64 by (dist, idx) ascending
    for (int k = 2; k <= 64; k <<= 1) {
        for (int j = k >> 1; j > 0; j >>= 1) {
            int p = tid ^ j;
            if (p > tid) {
                float d1 = ds[tid], d2 = ds[p];
                int i1 = isx[tid], i2 = isx[p];
                bool up = (tid & k) == 0;
                bool gt = (d1 > d2) || (d1 == d2 && i1 > i2);
                if (up ? gt : !gt) {
                    ds[tid] = d2; ds[p] = d1;
                    isx[tid] = i2; isx[p] = i1;
                }
            }
            __syncthreads();
        }
    }

    float wgt = 0.f, wv = 0.f;
    if (tid < NK) {
        wgt = 1.f / (ds[tid] + 1e-7f);
        wv = wgt * vals[isx[tid]];
    }
    float ws = warp_allred(wgt), vs = warp_allred(wv);
    if ((tid & 31) == 0) { part[tid >> 5] = ws; part[2 + (tid >> 5)] = vs; }
    __syncthreads();
    if (tid == 0) {
        float W = part[0] + part[1], V = part[2] + part[3];
        out[row] = 0.9f * (V / W) + 0.1f * net[row];
    }
}

// ---------------- launch ----------------
extern "C" void kernel_launch(void* const* d_in, const int* in_sizes, int n_in,
                              void* d_out, int out_size) {
    const float* states     = (const float*)d_in[0];
    const float* W1         = (const float*)d_in[1];
    const float* b1         = (const float*)d_in[2];
    const float* W2         = (const float*)d_in[3];
    const float* b2         = (const float*)d_in[4];
    const float* ln_g       = (const float*)d_in[5];
    const float* ln_b       = (const float*)d_in[6];
    const float* mem_keys   = (const float*)d_in[7];
    const float* mem_values = (const float*)d_in[8];
    const float* V1         = (const float*)d_in[9];
    const float* c1         = (const float*)d_in[10];
    const float* V2         = (const float*)d_in[11];
    const float* c2         = (const float*)d_in[12];
    const float* V3         = (const float*)d_in[13];
    const float* c3         = (const float*)d_in[14];
    float* out = (float*)d_out;

    void *ph, *pqpre, *pq, *pq2, *pk2, *pv1, *pv2, *pnet, *pk16, *pdist, *ptmin, *pcand;
    cudaGetSymbolAddress(&ph, g_h);
    cudaGetSymbolAddress(&pqpre, g_qpre);
    cudaGetSymbolAddress(&pq, g_q);
    cudaGetSymbolAddress(&pq2, g_q2);
    cudaGetSymbolAddress(&pk2, g_k2);
    cudaGetSymbolAddress(&pv1, g_v1);
    cudaGetSymbolAddress(&pv2, g_v2);
    cudaGetSymbolAddress(&pnet, g_net);
    cudaGetSymbolAddress(&pk16, g_keys16);
    cudaGetSymbolAddress(&pdist, g_dist);
    cudaGetSymbolAddress(&ptmin, g_tmin);
    cudaGetSymbolAddress(&pcand, g_cand);

    cudaFuncSetAttribute(p1_kernel, cudaFuncAttributeMaxDynamicSharedMemorySize, SM_TOT);

    cvtk2_kernel<<<NM / 8, 256>>>(mem_keys, (__nv_bfloat16*)pk16, (float*)pk2);          // 1

    gemmz_kernel<<<dim3(NH / 64, NB / 64, 2), 256>>>(states, states, W1, V1, b1, c1,
                                                     (float*)ph, (float*)pv1, 3,
                                                     NB, NH, NS);                        // 2
    gemmz_kernel<<<dim3(ND / 64, NB / 64, 2), 256>>>((const float*)ph, (const float*)pv1,
                                                     W2, V2, b2, c2,
                                                     (float*)pqpre, (float*)pv2, 2,
                                                     NB, ND, NH);                        // 3

    ln_kernel<<<NB / 8, 256>>>((const float*)pqpre, ln_g, ln_b, (float*)pq, (float*)pq2);// 4
    net_kernel<<<NB / 8, 256>>>((const float*)pv2, V3, c3, (float*)pnet);                // 5

    p1_kernel<<<dim3(NSPLIT, NB / 128), 512, SM_TOT>>>((const float*)pq,                 // 6
                                                       (const __nv_bfloat16*)pk16,
                                                       (const float*)pk2,
                                                       (__half*)pdist, (__half*)ptmin);

    sel_kernel<<<NB / 8, 256>>>((const __half*)pdist, (const __half*)ptmin, (int*)pcand);// 7

    p2_kernel<<<NB, 64>>>((const float*)pq, (const float*)pq2, (const float*)pk2,
                          mem_keys, mem_values, (const float*)pnet,
                          (const int*)pcand, out);                                       // 8
}

// round 16
// speedup vs baseline: 1.0926x; 1.0565x over previous
#include <cuda_runtime.h>
#include <cuda_bf16.h>
#include <cuda_fp16.h>
#include <cstdint>
#include <cstddef>

#define NB 4096
#define NS 544
#define NH 256
#define ND 128
#define NM 50000
#define NK 50
#define TILEN 128
#define NTIL 391         // ceil(50000/128)
#define NBLK 782         // NTIL * 2 blocks of 64 keys
#define CHT 17           // tiles per work item
#define NCHK 23          // items per q-block (23*17 = 391)
#define NITEM 736        // 32 q-blocks * 23
#define F_INF __int_as_float(0x7f800000)

// ---------------- scratch (static device globals; no allocations) ----------
__device__ float g_h[NB * NH];
__device__ float g_qpre[NB * ND];
__device__ float g_q[NB * ND];
__device__ float g_q2[NB];
__device__ float g_k2[NM];
__device__ float g_v1[NB * NH];
__device__ float g_v2[NB * ND];
__device__ float g_net[NB];
__device__ __nv_bfloat16 g_keys16[NM * ND];
__device__ __half g_dist[(size_t)NB * NM];     // 409.6 MB fp16 score matrix
__device__ __half g_tmin[(size_t)NB * NBLK];   // block minima
__device__ int g_cand[NB * 64];

// ---------------- helpers ----------------
__device__ __forceinline__ uint32_t smem_u32(const void* p) {
    uint32_t a;
    asm("{ .reg .u64 t; cvta.to.shared.u64 t, %1; cvt.u32.u64 %0, t; }" : "=r"(a) : "l"(p));
    return a;
}
__device__ __forceinline__ void cp16(uint32_t dst, const void* src) {
    asm volatile("cp.async.ca.shared.global [%0], [%1], 16;\n" :: "r"(dst), "l"(src));
}
__device__ __forceinline__ float warp_allred(float v) {
#pragma unroll
    for (int o = 16; o; o >>= 1) v += __shfl_xor_sync(0xffffffffu, v, o);
    return v;
}
__device__ __forceinline__ void ldsm_x4(uint32_t& r0, uint32_t& r1, uint32_t& r2,
                                        uint32_t& r3, uint32_t addr) {
    asm volatile("ldmatrix.sync.aligned.m8n8.x4.shared.b16 {%0,%1,%2,%3}, [%4];"
                 : "=r"(r0), "=r"(r1), "=r"(r2), "=r"(r3) : "r"(addr));
}
__device__ __forceinline__ void mma_bf16(float* c, const uint32_t* a, uint32_t b0, uint32_t b1) {
    asm volatile("mma.sync.aligned.m16n8k16.row.col.f32.bf16.bf16.f32 "
                 "{%0,%1,%2,%3}, {%4,%5,%6,%7}, {%8,%9}, {%0,%1,%2,%3};"
                 : "+f"(c[0]), "+f"(c[1]), "+f"(c[2]), "+f"(c[3])
                 : "r"(a[0]), "r"(a[1]), "r"(a[2]), "r"(a[3]), "r"(b0), "r"(b1));
}

// warp-cooperative top-64 (2 register slots per lane)
__device__ __forceinline__ void ins64(float& s0, float& s1, int& i0, int& i1,
                                      float& mx, float fv, int id, int lane) {
    const unsigned FULL = 0xffffffffu;
    for (;;) {
        unsigned m = __ballot_sync(FULL, fv < mx);
        if (!m) break;
        int src = __ffs(m) - 1;
        float ff = __shfl_sync(FULL, fv, src);
        int ii = __shfl_sync(FULL, id, src);
        float lm = fmaxf(s0, s1);
        float M = lm;
#pragma unroll
        for (int o = 16; o; o >>= 1) M = fmaxf(M, __shfl_xor_sync(FULL, M, o));
        unsigned hm = __ballot_sync(FULL, lm == M);
        int hl = __ffs(hm) - 1;
        if (lane == hl) {
            if (s0 >= s1) { s0 = ff; i0 = ii; }
            else          { s1 = ff; i1 = ii; }
        }
        lm = fmaxf(s0, s1);
#pragma unroll
        for (int o = 16; o; o >>= 1) lm = fmaxf(lm, __shfl_xor_sync(FULL, lm, o));
        mx = lm;
        if (lane == src) fv = F_INF;
    }
}

// ---------------- fused key conversion + k2 (one pass over mem_keys) -------
__global__ void cvtk2_kernel(const float* __restrict__ keys, __nv_bfloat16* __restrict__ out,
                             float* __restrict__ k2) {
    int w = (blockIdx.x * blockDim.x + threadIdx.x) >> 5;
    int lane = threadIdx.x & 31;
    float4 v = *(const float4*)(keys + (size_t)w * ND + lane * 4);
    float s = v.x * v.x + v.y * v.y + v.z * v.z + v.w * v.w;
    s = warp_allred(s);
    if (lane == 0) k2[w] = s;
    __nv_bfloat162 a = __floats2bfloat162_rn(v.x, v.y);
    __nv_bfloat162 b = __floats2bfloat162_rn(v.z, v.w);
    uint2 o;
    o.x = *(uint32_t*)&a;
    o.y = *(uint32_t*)&b;
    *(uint2*)(out + (size_t)w * ND + lane * 4) = o;
}

// ---------------- z-batched encoder GEMM, cp.async double-buffered ---------
__global__ void gemmz_kernel(const float* __restrict__ A0, const float* __restrict__ A1,
                             const float* __restrict__ W0, const float* __restrict__ W1b,
                             const float* __restrict__ b0, const float* __restrict__ b1b,
                             float* __restrict__ C0, float* __restrict__ C1,
                             int relu_mask, int Md, int Nd, int Kd) {
    const int z = blockIdx.z;
    const float* A = z ? A1 : A0;
    const float* W = z ? W1b : W0;
    const float* bias = z ? b1b : b0;
    float* C = z ? C1 : C0;
    const int relu = (relu_mask >> z) & 1;

    __shared__ __align__(16) float As[2][64][20];
    __shared__ __align__(16) float Bs[2][16][64];
    const int tid = threadIdx.x;
    const int tn = tid & 15, tm = tid >> 4;
    const int row0 = blockIdx.y << 6, col0 = blockIdx.x << 6;
    const int arow = tid >> 2, acol = (tid & 3) << 2;
    const int brow = tid >> 4, bcol = (tid & 15) << 2;
    const int NSTG = Kd >> 4;

    const uint32_t sa = smem_u32(&As[0][0][0]);
    const uint32_t sbs = smem_u32(&Bs[0][0][0]);

    cp16(sa + (arow * 20 + acol) * 4, A + (size_t)(row0 + arow) * Kd + acol);
    cp16(sbs + (brow * 64 + bcol) * 4, W + (size_t)brow * Nd + col0 + bcol);
    asm volatile("cp.async.commit_group;\n" ::: "memory");

    float acc[4][4] = {};
    for (int st = 0; st < NSTG; ++st) {
        const int buf = st & 1;
        if (st + 1 < NSTG) {
            const int nb = (st + 1) & 1;
            const int k0 = (st + 1) << 4;
            cp16(sa + (nb * 64 * 20 + arow * 20 + acol) * 4,
                 A + (size_t)(row0 + arow) * Kd + k0 + acol);
            cp16(sbs + (nb * 16 * 64 + brow * 64 + bcol) * 4,
                 W + (size_t)(k0 + brow) * Nd + col0 + bcol);
            asm volatile("cp.async.commit_group;\n" ::: "memory");
            asm volatile("cp.async.wait_group 1;\n" ::: "memory");
        } else {
            asm volatile("cp.async.wait_group 0;\n" ::: "memory");
        }
        __syncthreads();
#pragma unroll
        for (int kk = 0; kk < 16; ++kk) {
            float aa[4];
#pragma unroll
            for (int i = 0; i < 4; ++i) aa[i] = As[buf][tm * 4 + i][kk];
            float4 b4 = *(float4*)&Bs[buf][kk][tn * 4];
            float bb[4] = {b4.x, b4.y, b4.z, b4.w};
#pragma unroll
            for (int i = 0; i < 4; ++i)
#pragma unroll
                for (int j = 0; j < 4; ++j)
                    acc[i][j] = fmaf(aa[i], bb[j], acc[i][j]);
        }
        __syncthreads();
    }
    float4 bz = *(const float4*)(bias + col0 + tn * 4);
    float bb[4] = {bz.x, bz.y, bz.z, bz.w};
#pragma unroll
    for (int i = 0; i < 4; ++i) {
        float v0 = acc[i][0] + bb[0], v1 = acc[i][1] + bb[1];
        float v2 = acc[i][2] + bb[2], v3 = acc[i][3] + bb[3];
        if (relu) {
            v0 = fmaxf(v0, 0.f); v1 = fmaxf(v1, 0.f);
            v2 = fmaxf(v2, 0.f); v3 = fmaxf(v3, 0.f);
        }
        float4 o; o.x = v0; o.y = v1; o.z = v2; o.w = v3;
        *(float4*)(C + (size_t)(row0 + tm * 4 + i) * Nd + col0 + tn * 4) = o;
    }
}

__global__ void ln_kernel(const float* __restrict__ x, const float* __restrict__ g,
                          const float* __restrict__ b, float* __restrict__ q,
                          float* __restrict__ q2) {
    int row = (blockIdx.x * blockDim.x + threadIdx.x) >> 5;
    int lane = threadIdx.x & 31;
    float4 v = *(const float4*)(x + (size_t)row * ND + lane * 4);
    float mu = warp_allred(v.x + v.y + v.z + v.w) * (1.f / 128.f);
    float d0 = v.x - mu, d1 = v.y - mu, d2 = v.z - mu, d3 = v.w - mu;
    float var = warp_allred(d0 * d0 + d1 * d1 + d2 * d2 + d3 * d3) * (1.f / 128.f);
    float inv = rsqrtf(var + 1e-5f);
    float4 gg = *(const float4*)(g + lane * 4);
    float4 bb = *(const float4*)(b + lane * 4);
    float4 o;
    o.x = d0 * inv * gg.x + bb.x;
    o.y = d1 * inv * gg.y + bb.y;
    o.z = d2 * inv * gg.z + bb.z;
    o.w = d3 * inv * gg.w + bb.w;
    *(float4*)(q + (size_t)row * ND + lane * 4) = o;
    float qq = warp_allred(o.x * o.x + o.y * o.y + o.z * o.z + o.w * o.w);
    if (lane == 0) q2[row] = qq;
}

__global__ void net_kernel(const float* __restrict__ v2, const float* __restrict__ V3,
                           const float* __restrict__ c3, float* __restrict__ net) {
    int row = (blockIdx.x * blockDim.x + threadIdx.x) >> 5;
    int lane = threadIdx.x & 31;
    float4 a = *(const float4*)(v2 + (size_t)row * ND + lane * 4);
    float4 w = *(const float4*)(V3 + lane * 4);
    float s = warp_allred(a.x * w.x + a.y * w.y + a.z * w.z + a.w * w.w);
    if (lane == 0) net[row] = s + c3[0];
}

// ---------------- phase 1: flattened-work bf16 mma GEMM --------------------
#define SM_B    0        // 2 x 32768: key tiles, swizzled (row*256 + (u^(row&7))*16)
#define SM_QS   65536    // 32768: q bf16 staging
#define SM_K2   98304    // 2 x 512
#define SM_TOT  99328

__device__ __forceinline__ void p1_load_tile(int g, int buf, int tid, uint32_t sb,
                                             float* k2s, const __nv_bfloat16* keys16,
                                             const float* k2g) {
    const int m0t = g * TILEN;
#pragma unroll
    for (int it = 0; it < 4; ++it) {
        int idx = tid + (it << 9);
        int row = idx >> 4, u = idx & 15;
        int gm = m0t + row;
        if (gm < NM)
            cp16(sb + SM_B + buf * 32768 + row * 256 + ((u ^ (row & 7)) << 4),
                 keys16 + (size_t)gm * ND + u * 8);
    }
    if (tid < 32) {
        int g0 = m0t + tid * 4;
        if (g0 + 3 < NM) {
            cp16(sb + SM_K2 + buf * 512 + (tid << 4), k2g + g0);
        } else {
#pragma unroll
            for (int u2 = 0; u2 < 4; ++u2) {
                int gg = g0 + u2;
                k2s[buf * 128 + tid * 4 + u2] = (gg < NM) ? __ldg(k2g + gg) : F_INF;
            }
        }
    }
    asm volatile("cp.async.commit_group;\n" ::: "memory");
}

__global__ void __launch_bounds__(512, 1)
p1_kernel(const float* __restrict__ q, const __nv_bfloat16* __restrict__ keys16,
          const float* __restrict__ k2g, __half* __restrict__ dist,
          __half* __restrict__ tmin) {
    extern __shared__ __align__(16) char sm[];
    const uint32_t sb = smem_u32(sm);
    float* k2s = (float*)(sm + SM_K2);
    const unsigned FULL = 0xffffffffu;

    const int tid = threadIdx.x;
    const int w = tid >> 5;
    const int lt = tid & 31;
    const int wr = w & 7;          // q-row group
    const int wh = w >> 3;         // key half (0/1)

    const int it0 = blockIdx.x * 5;
    const int it1 = min(it0 + 5, NITEM);

    const int nbase = (lt >> 4) * 8 + (lt & 7);
    const int hh = (lt >> 3) & 1;
    const int r0 = wr * 16 + (lt >> 2);
    const int cbase = (lt & 3) << 1;

    uint32_t af[8][4];
    int cur_qb = -1;
    __half* drow0 = dist;
    __half* drow1 = dist;
    size_t trow = 0;

    for (int item = it0; item < it1; ++item) {
        const int qb = item / NCHK;
        const int chunk = item - qb * NCHK;
        const int gbase = chunk * CHT;

        if (qb != cur_qb) {
            __syncthreads();   // all warps done with previous staging/compute
            // stage q block as bf16 (swizzled)
#pragma unroll
            for (int itr = 0; itr < 4; ++itr) {
                int idx = tid + (itr << 9);
                int row = idx >> 4, u = idx & 15;
                const float* src = q + (size_t)(qb * 128 + row) * ND + u * 8;
                float4 v0 = *(const float4*)src;
                float4 v1 = *(const float4*)(src + 4);
                __nv_bfloat162 p0 = __floats2bfloat162_rn(v0.x, v0.y);
                __nv_bfloat162 p1 = __floats2bfloat162_rn(v0.z, v0.w);
                __nv_bfloat162 p2 = __floats2bfloat162_rn(v1.x, v1.y);
                __nv_bfloat162 p3 = __floats2bfloat162_rn(v1.z, v1.w);
                uint4 pk;
                pk.x = *(uint32_t*)&p0; pk.y = *(uint32_t*)&p1;
                pk.z = *(uint32_t*)&p2; pk.w = *(uint32_t*)&p3;
                *(uint4*)(sm + SM_QS + row * 256 + ((u ^ (row & 7)) << 4)) = pk;
            }
            __syncthreads();
            {
                int mrow = wr * 16 + (lt & 7) + ((lt >> 3) & 1) * 8;
                int kh = lt >> 4;
                uint32_t abase = sb + SM_QS + mrow * 256;
                int msw = mrow & 7;
#pragma unroll
                for (int kk = 0; kk < 8; ++kk)
                    ldsm_x4(af[kk][0], af[kk][1], af[kk][2], af[kk][3],
                            abase + ((((kk << 1) | kh) ^ msw) << 4));
            }
            cur_qb = qb;
            drow0 = dist + (size_t)(qb * 128 + r0) * NM;
            drow1 = drow0 + (size_t)8 * NM;
            trow = (size_t)(qb * 128 + r0) * NBLK;
        }

        p1_load_tile(gbase, 0, tid, sb, k2s, keys16, k2g);

        for (int tt = 0; tt < CHT; ++tt) {
            const int g = gbase + tt;
            const int buf = tt & 1;
            asm volatile("cp.async.wait_group 0;\n" ::: "memory");
            __syncthreads();
            if (tt + 1 < CHT) p1_load_tile(g + 1, (tt + 1) & 1, tid, sb, k2s, keys16, k2g);

            float acc[8][4];
#pragma unroll
            for (int j = 0; j < 8; ++j)
#pragma unroll
                for (int e = 0; e < 4; ++e) acc[j][e] = 0.f;

            const uint32_t bbase = sb + SM_B + buf * 32768 + wh * 16384;
#pragma unroll
            for (int kk = 0; kk < 8; ++kk) {
#pragma unroll
                for (int jp = 0; jp < 4; ++jp) {
                    int n = jp * 16 + nbase;
                    uint32_t addr = bbase + n * 256 + ((((kk << 1) | hh) ^ (n & 7)) << 4);
                    uint32_t b0, b1, b2, b3;
                    ldsm_x4(b0, b1, b2, b3, addr);
                    mma_bf16(acc[2 * jp], af[kk], b0, b1);
                    mma_bf16(acc[2 * jp + 1], af[kk], b2, b3);
                }
            }

            // stream scores (k2 - 2*dot) to HBM as fp16, tracking block minima
            const int m0t = g * TILEN;
            float mn0 = F_INF, mn1 = F_INF;
#pragma unroll
            for (int j = 0; j < 8; ++j) {
                int c = wh * 64 + j * 8 + cbase;
                int gc = m0t + c;
                if (gc < NM) {
                    float2 kk2 = *(float2*)(k2s + buf * 128 + c);
                    float2 s0, s1;
                    s0.x = fmaf(acc[j][0], -2.f, kk2.x);
                    s0.y = fmaf(acc[j][1], -2.f, kk2.y);
                    s1.x = fmaf(acc[j][2], -2.f, kk2.x);
                    s1.y = fmaf(acc[j][3], -2.f, kk2.y);
                    mn0 = fminf(mn0, fminf(s0.x, s0.y));
                    mn1 = fminf(mn1, fminf(s1.x, s1.y));
                    *(__half2*)(drow0 + gc) = __float22half2_rn(s0);
                    *(__half2*)(drow1 + gc) = __float22half2_rn(s1);
                }
            }
            mn0 = fminf(mn0, __shfl_xor_sync(FULL, mn0, 1));
            mn0 = fminf(mn0, __shfl_xor_sync(FULL, mn0, 2));
            mn1 = fminf(mn1, __shfl_xor_sync(FULL, mn1, 1));
            mn1 = fminf(mn1, __shfl_xor_sync(FULL, mn1, 2));
            if ((lt & 3) == 0) {
                size_t base = trow + g * 2 + wh;
                tmin[base] = __float2half(mn0);
                tmin[base + (size_t)8 * NBLK] = __float2half(mn1);
            }
        }
    }
}

// ---------------- selection: block-min prune + exact top-64 ---------------
__global__ void __launch_bounds__(256)
sel_kernel(const __half* __restrict__ dist, const __half* __restrict__ tmin,
           int* __restrict__ cand) {
    const unsigned FULL = 0xffffffffu;
    __shared__ int bids_s[8][64];
    const int wrp = threadIdx.x >> 5;
    const int wid = (blockIdx.x * blockDim.x + threadIdx.x) >> 5;  // row 0..4095
    const int lane = threadIdx.x & 31;

    // ---- pass A: top-64 of block minima (block b covers keys [b*64, b*64+64)) ----
    float s0 = F_INF, s1 = F_INF;
    int i0 = 0, i1 = 0;
    float mx = F_INF;
    const __half* trow = tmin + (size_t)wid * NBLK;
    for (int i = 0; i < 25; ++i) {
        int idx = i * 32 + lane;
        float fv = (idx < NBLK) ? __half2float(trow[idx]) : F_INF;
        if (__ballot_sync(FULL, fv < mx))
            ins64(s0, s1, i0, i1, mx, fv, idx, lane);
    }
    bids_s[wrp][lane * 2] = i0;
    bids_s[wrp][lane * 2 + 1] = i1;
    __syncwarp();

    // ---- pass B: exact top-64 over the 64 candidate blocks ----
    s0 = F_INF; s1 = F_INF; i0 = 0; i1 = 0; mx = F_INF;
    const __half* row = dist + (size_t)wid * NM;
    for (int b = 0; b < 64; ++b) {
        int key = bids_s[wrp][b] * 64 + lane * 2;
        float f0 = F_INF, f1 = F_INF;
        if (key < NM) {
            float2 ff = __half22float2(*(const __half2*)(row + key));
            f0 = ff.x; f1 = ff.y;
        }
        if (__ballot_sync(FULL, fminf(f0, f1) < mx)) {
            ins64(s0, s1, i0, i1, mx, f0, key, lane);
            ins64(s0, s1, i0, i1, mx, f1, key + 1, lane);
        }
    }
    int* dst = cand + (size_t)wid * 64;
    dst[lane * 2] = i0;
    dst[lane * 2 + 1] = i1;
}

// ---------------- phase 2: exact fp32 rescore + top-50 + output ------------
__global__ void __launch_bounds__(64)
p2_kernel(const float* __restrict__ q, const float* __restrict__ q2g,
          const float* __restrict__ k2g, const float* __restrict__ keys,
          const float* __restrict__ vals, const float* __restrict__ net,
          const int* __restrict__ cand, float* __restrict__ out) {
    __shared__ float qs[128];
    __shared__ float ds[64];
    __shared__ int isx[64];
    __shared__ float part[4];
    const int row = blockIdx.x;
    const int tid = threadIdx.x;
    qs[tid] = q[(size_t)row * ND + tid];
    qs[tid + 64] = q[(size_t)row * ND + tid + 64];
    __syncthreads();

    int c = cand[(size_t)row * 64 + tid];
    const float4* kr = (const float4*)(keys + (size_t)c * ND);
    float dot = 0.f;
#pragma unroll 8
    for (int i = 0; i < 32; ++i) {
        float4 k4 = kr[i];
        float4 q4 = *(const float4*)(qs + i * 4);
        dot = fmaf(k4.x, q4.x, dot);
        dot = fmaf(k4.y, q4.y, dot);
        dot = fmaf(k4.z, q4.z, dot);
        dot = fmaf(k4.w, q4.w, dot);
    }
    ds[tid] = q2g[row] + k2g[c] - 2.f * dot;
    isx[tid] = c;
    __syncthreads();

    // bitonic sort 64 by (dist, idx) ascending
    for (int k = 2; k <= 64; k <<= 1) {
        for (int j = k >> 1; j > 0; j >>= 1) {
            int p = tid ^ j;
            if (p > tid) {
                float d1 = ds[tid], d2 = ds[p];
                int i1 = isx[tid], i2 = isx[p];
                bool up = (tid & k) == 0;
                bool gt = (d1 > d2) || (d1 == d2 && i1 > i2);
                if (up ? gt : !gt) {
                    ds[tid] = d2; ds[p] = d1;
                    isx[tid] = i2; isx[p] = i1;
                }
            }
            __syncthreads();
        }
    }

    float wgt = 0.f, wv = 0.f;
    if (tid < NK) {
        wgt = 1.f / (ds[tid] + 1e-7f);
        wv = wgt * vals[isx[tid]];
    }
    float ws = warp_allred(wgt), vs = warp_allred(wv);
    if ((tid & 31) == 0) { part[tid >> 5] = ws; part[2 + (tid >> 5)] = vs; }
    __syncthreads();
    if (tid == 0) {
        float W = part[0] + part[1], V = part[2] + part[3];
        out[row] = 0.9f * (V / W) + 0.1f * net[row];
    }
}

// ---------------- launch ----------------
extern "C" void kernel_launch(void* const* d_in, const int* in_sizes, int n_in,
                              void* d_out, int out_size) {
    const float* states     = (const float*)d_in[0];
    const float* W1         = (const float*)d_in[1];
    const float* b1         = (const float*)d_in[2];
    const float* W2         = (const float*)d_in[3];
    const float* b2         = (const float*)d_in[4];
    const float* ln_g       = (const float*)d_in[5];
    const float* ln_b       = (const float*)d_in[6];
    const float* mem_keys   = (const float*)d_in[7];
    const float* mem_values = (const float*)d_in[8];
    const float* V1         = (const float*)d_in[9];
    const float* c1         = (const float*)d_in[10];
    const float* V2         = (const float*)d_in[11];
    const float* c2         = (const float*)d_in[12];
    const float* V3         = (const float*)d_in[13];
    const float* c3         = (const float*)d_in[14];
    float* out = (float*)d_out;

    void *ph, *pqpre, *pq, *pq2, *pk2, *pv1, *pv2, *pnet, *pk16, *pdist, *ptmin, *pcand;
    cudaGetSymbolAddress(&ph, g_h);
    cudaGetSymbolAddress(&pqpre, g_qpre);
    cudaGetSymbolAddress(&pq, g_q);
    cudaGetSymbolAddress(&pq2, g_q2);
    cudaGetSymbolAddress(&pk2, g_k2);
    cudaGetSymbolAddress(&pv1, g_v1);
    cudaGetSymbolAddress(&pv2, g_v2);
    cudaGetSymbolAddress(&pnet, g_net);
    cudaGetSymbolAddress(&pk16, g_keys16);
    cudaGetSymbolAddress(&pdist, g_dist);
    cudaGetSymbolAddress(&ptmin, g_tmin);
    cudaGetSymbolAddress(&pcand, g_cand);

    cudaFuncSetAttribute(p1_kernel, cudaFuncAttributeMaxDynamicSharedMemorySize, SM_TOT);

    cvtk2_kernel<<<NM / 8, 256>>>(mem_keys, (__nv_bfloat16*)pk16, (float*)pk2);          // 1

    gemmz_kernel<<<dim3(NH / 64, NB / 64, 2), 256>>>(states, states, W1, V1, b1, c1,
                                                     (float*)ph, (float*)pv1, 3,
                                                     NB, NH, NS);                        // 2
    gemmz_kernel<<<dim3(ND / 64, NB / 64, 2), 256>>>((const float*)ph, (const float*)pv1,
                                                     W2, V2, b2, c2,
                                                     (float*)pqpre, (float*)pv2, 2,
                                                     NB, ND, NH);                        // 3

    ln_kernel<<<NB / 8, 256>>>((const float*)pqpre, ln_g, ln_b, (float*)pq, (float*)pq2);// 4
    net_kernel<<<NB / 8, 256>>>((const float*)pv2, V3, c3, (float*)pnet);                // 5

    p1_kernel<<<148, 512, SM_TOT>>>((const float*)pq,                                    // 6
                                    (const __nv_bfloat16*)pk16,
                                    (const float*)pk2,
                                    (__half*)pdist, (__half*)ptmin);

    sel_kernel<<<NB / 8, 256>>>((const __half*)pdist, (const __half*)ptmin, (int*)pcand);// 7

    p2_kernel<<<NB, 64>>>((const float*)pq, (const float*)pq2, (const float*)pk2,
                          mem_keys, mem_values, (const float*)pnet,
                          (const int*)pcand, out);                                       // 8
}

// round 17
// speedup vs baseline: 1.0931x; 1.0004x over previous
#include <cuda_runtime.h>
#include <cuda_bf16.h>
#include <cuda_fp16.h>
#include <cstdint>
#include <cstddef>

#define NB 4096
#define NS 544
#define NH 256
#define ND 128
#define NM 50000
#define NK 50
#define TILEN 128
#define NTIL 391         // ceil(50000/128)
#define NBLK 782         // NTIL * 2 blocks of 64 keys
#define CHT 17           // tiles per work item
#define NCHK 23          // items per q-block (23*17 = 391)
#define NITEM 736        // 32 q-blocks * 23
#define F_INF __int_as_float(0x7f800000)

// ---------------- scratch (static device globals; no allocations) ----------
__device__ float g_h[NB * NH];
__device__ float g_qpre[NB * ND];
__device__ float g_q[NB * ND];
__device__ float g_q2[NB];
__device__ float g_k2[NM];
__device__ float g_v1[NB * NH];
__device__ float g_v2[NB * ND];
__device__ float g_net[NB];
__device__ __nv_bfloat16 g_keys16[NM * ND];
__device__ __half g_dist[(size_t)NB * NM];     // 409.6 MB fp16 score matrix
__device__ __half g_tmin[(size_t)NB * NBLK];   // block minima
__device__ int g_cand[NB * 64];

// ---------------- side stream + events (host objects, created at init) -----
static cudaStream_t g_s1;
static cudaEvent_t g_e0, g_ek, g_ev;
namespace {
struct _StrInit {
    _StrInit() {
        cudaStreamCreateWithFlags(&g_s1, cudaStreamNonBlocking);
        cudaEventCreateWithFlags(&g_e0, cudaEventDisableTiming);
        cudaEventCreateWithFlags(&g_ek, cudaEventDisableTiming);
        cudaEventCreateWithFlags(&g_ev, cudaEventDisableTiming);
    }
};
_StrInit _strInit;
}

// ---------------- helpers ----------------
__device__ __forceinline__ uint32_t smem_u32(const void* p) {
    uint32_t a;
    asm("{ .reg .u64 t; cvta.to.shared.u64 t, %1; cvt.u32.u64 %0, t; }" : "=r"(a) : "l"(p));
    return a;
}
__device__ __forceinline__ void cp16(uint32_t dst, const void* src) {
    asm volatile("cp.async.ca.shared.global [%0], [%1], 16;\n" :: "r"(dst), "l"(src));
}
__device__ __forceinline__ float warp_allred(float v) {
#pragma unroll
    for (int o = 16; o; o >>= 1) v += __shfl_xor_sync(0xffffffffu, v, o);
    return v;
}
__device__ __forceinline__ void ldsm_x4(uint32_t& r0, uint32_t& r1, uint32_t& r2,
                                        uint32_t& r3, uint32_t addr) {
    asm volatile("ldmatrix.sync.aligned.m8n8.x4.shared.b16 {%0,%1,%2,%3}, [%4];"
                 : "=r"(r0), "=r"(r1), "=r"(r2), "=r"(r3) : "r"(addr));
}
__device__ __forceinline__ void mma_bf16(float* c, const uint32_t* a, uint32_t b0, uint32_t b1) {
    asm volatile("mma.sync.aligned.m16n8k16.row.col.f32.bf16.bf16.f32 "
                 "{%0,%1,%2,%3}, {%4,%5,%6,%7}, {%8,%9}, {%0,%1,%2,%3};"
                 : "+f"(c[0]), "+f"(c[1]), "+f"(c[2]), "+f"(c[3])
                 : "r"(a[0]), "r"(a[1]), "r"(a[2]), "r"(a[3]), "r"(b0), "r"(b1));
}

// warp-cooperative top-64 (2 register slots per lane)
__device__ __forceinline__ void ins64(float& s0, float& s1, int& i0, int& i1,
                                      float& mx, float fv, int id, int lane) {
    const unsigned FULL = 0xffffffffu;
    for (;;) {
        unsigned m = __ballot_sync(FULL, fv < mx);
        if (!m) break;
        int src = __ffs(m) - 1;
        float ff = __shfl_sync(FULL, fv, src);
        int ii = __shfl_sync(FULL, id, src);
        float lm = fmaxf(s0, s1);
        float M = lm;
#pragma unroll
        for (int o = 16; o; o >>= 1) M = fmaxf(M, __shfl_xor_sync(FULL, M, o));
        unsigned hm = __ballot_sync(FULL, lm == M);
        int hl = __ffs(hm) - 1;
        if (lane == hl) {
            if (s0 >= s1) { s0 = ff; i0 = ii; }
            else          { s1 = ff; i1 = ii; }
        }
        lm = fmaxf(s0, s1);
#pragma unroll
        for (int o = 16; o; o >>= 1) lm = fmaxf(lm, __shfl_xor_sync(FULL, lm, o));
        mx = lm;
        if (lane == src) fv = F_INF;
    }
}

// ---------------- fused key conversion + k2 (one pass over mem_keys) -------
__global__ void cvtk2_kernel(const float* __restrict__ keys, __nv_bfloat16* __restrict__ out,
                             float* __restrict__ k2) {
    int w = (blockIdx.x * blockDim.x + threadIdx.x) >> 5;
    int lane = threadIdx.x & 31;
    float4 v = *(const float4*)(keys + (size_t)w * ND + lane * 4);
    float s = v.x * v.x + v.y * v.y + v.z * v.z + v.w * v.w;
    s = warp_allred(s);
    if (lane == 0) k2[w] = s;
    __nv_bfloat162 a = __floats2bfloat162_rn(v.x, v.y);
    __nv_bfloat162 b = __floats2bfloat162_rn(v.z, v.w);
    uint2 o;
    o.x = *(uint32_t*)&a;
    o.y = *(uint32_t*)&b;
    *(uint2*)(out + (size_t)w * ND + lane * 4) = o;
}

// ---------------- z-batched encoder GEMM, cp.async double-buffered ---------
__global__ void gemmz_kernel(const float* __restrict__ A0, const float* __restrict__ A1,
                             const float* __restrict__ W0, const float* __restrict__ W1b,
                             const float* __restrict__ b0, const float* __restrict__ b1b,
                             float* __restrict__ C0, float* __restrict__ C1,
                             int relu_mask, int Md, int Nd, int Kd) {
    const int z = blockIdx.z;
    const float* A = z ? A1 : A0;
    const float* W = z ? W1b : W0;
    const float* bias = z ? b1b : b0;
    float* C = z ? C1 : C0;
    const int relu = (relu_mask >> z) & 1;

    __shared__ __align__(16) float As[2][64][20];
    __shared__ __align__(16) float Bs[2][16][64];
    const int tid = threadIdx.x;
    const int tn = tid & 15, tm = tid >> 4;
    const int row0 = blockIdx.y << 6, col0 = blockIdx.x << 6;
    const int arow = tid >> 2, acol = (tid & 3) << 2;
    const int brow = tid >> 4, bcol = (tid & 15) << 2;
    const int NSTG = Kd >> 4;

    const uint32_t sa = smem_u32(&As[0][0][0]);
    const uint32_t sbs = smem_u32(&Bs[0][0][0]);

    cp16(sa + (arow * 20 + acol) * 4, A + (size_t)(row0 + arow) * Kd + acol);
    cp16(sbs + (brow * 64 + bcol) * 4, W + (size_t)brow * Nd + col0 + bcol);
    asm volatile("cp.async.commit_group;\n" ::: "memory");

    float acc[4][4] = {};
    for (int st = 0; st < NSTG; ++st) {
        const int buf = st & 1;
        if (st + 1 < NSTG) {
            const int nb = (st + 1) & 1;
            const int k0 = (st + 1) << 4;
            cp16(sa + (nb * 64 * 20 + arow * 20 + acol) * 4,
                 A + (size_t)(row0 + arow) * Kd + k0 + acol);
            cp16(sbs + (nb * 16 * 64 + brow * 64 + bcol) * 4,
                 W + (size_t)(k0 + brow) * Nd + col0 + bcol);
            asm volatile("cp.async.commit_group;\n" ::: "memory");
            asm volatile("cp.async.wait_group 1;\n" ::: "memory");
        } else {
            asm volatile("cp.async.wait_group 0;\n" ::: "memory");
        }
        __syncthreads();
#pragma unroll
        for (int kk = 0; kk < 16; ++kk) {
            float aa[4];
#pragma unroll
            for (int i = 0; i < 4; ++i) aa[i] = As[buf][tm * 4 + i][kk];
            float4 b4 = *(float4*)&Bs[buf][kk][tn * 4];
            float bb[4] = {b4.x, b4.y, b4.z, b4.w};
#pragma unroll
            for (int i = 0; i < 4; ++i)
#pragma unroll
                for (int j = 0; j < 4; ++j)
                    acc[i][j] = fmaf(aa[i], bb[j], acc[i][j]);
        }
        __syncthreads();
    }
    float4 bz = *(const float4*)(bias + col0 + tn * 4);
    float bb[4] = {bz.x, bz.y, bz.z, bz.w};
#pragma unroll
    for (int i = 0; i < 4; ++i) {
        float v0 = acc[i][0] + bb[0], v1 = acc[i][1] + bb[1];
        float v2 = acc[i][2] + bb[2], v3 = acc[i][3] + bb[3];
        if (relu) {
            v0 = fmaxf(v0, 0.f); v1 = fmaxf(v1, 0.f);
            v2 = fmaxf(v2, 0.f); v3 = fmaxf(v3, 0.f);
        }
        float4 o; o.x = v0; o.y = v1; o.z = v2; o.w = v3;
        *(float4*)(C + (size_t)(row0 + tm * 4 + i) * Nd + col0 + tn * 4) = o;
    }
}

__global__ void ln_kernel(const float* __restrict__ x, const float* __restrict__ g,
                          const float* __restrict__ b, float* __restrict__ q,
                          float* __restrict__ q2) {
    int row = (blockIdx.x * blockDim.x + threadIdx.x) >> 5;
    int lane = threadIdx.x & 31;
    float4 v = *(const float4*)(x + (size_t)row * ND + lane * 4);
    float mu = warp_allred(v.x + v.y + v.z + v.w) * (1.f / 128.f);
    float d0 = v.x - mu, d1 = v.y - mu, d2 = v.z - mu, d3 = v.w - mu;
    float var = warp_allred(d0 * d0 + d1 * d1 + d2 * d2 + d3 * d3) * (1.f / 128.f);
    float inv = rsqrtf(var + 1e-5f);
    float4 gg = *(const float4*)(g + lane * 4);
    float4 bb = *(const float4*)(b + lane * 4);
    float4 o;
    o.x = d0 * inv * gg.x + bb.x;
    o.y = d1 * inv * gg.y + bb.y;
    o.z = d2 * inv * gg.z + bb.z;
    o.w = d3 * inv * gg.w + bb.w;
    *(float4*)(q + (size_t)row * ND + lane * 4) = o;
    float qq = warp_allred(o.x * o.x + o.y * o.y + o.z * o.z + o.w * o.w);
    if (lane == 0) q2[row] = qq;
}

__global__ void net_kernel(const float* __restrict__ v2, const float* __restrict__ V3,
                           const float* __restrict__ c3, float* __restrict__ net) {
    int row = (blockIdx.x * blockDim.x + threadIdx.x) >> 5;
    int lane = threadIdx.x & 31;
    float4 a = *(const float4*)(v2 + (size_t)row * ND + lane * 4);
    float4 w = *(const float4*)(V3 + lane * 4);
    float s = warp_allred(a.x * w.x + a.y * w.y + a.z * w.z + a.w * w.w);
    if (lane == 0) net[row] = s + c3[0];
}

// ---------------- phase 1: flattened-work bf16 mma GEMM --------------------
#define SM_B    0        // 2 x 32768: key tiles, swizzled (row*256 + (u^(row&7))*16)
#define SM_QS   65536    // 32768: q bf16 staging
#define SM_K2   98304    // 2 x 512
#define SM_TOT  99328

__device__ __forceinline__ void p1_load_tile(int g, int buf, int tid, uint32_t sb,
                                             float* k2s, const __nv_bfloat16* keys16,
                                             const float* k2g) {
    const int m0t = g * TILEN;
#pragma unroll
    for (int it = 0; it < 4; ++it) {
        int idx = tid + (it << 9);
        int row = idx >> 4, u = idx & 15;
        int gm = m0t + row;
        if (gm < NM)
            cp16(sb + SM_B + buf * 32768 + row * 256 + ((u ^ (row & 7)) << 4),
                 keys16 + (size_t)gm * ND + u * 8);
    }
    if (tid < 32) {
        int g0 = m0t + tid * 4;
        if (g0 + 3 < NM) {
            cp16(sb + SM_K2 + buf * 512 + (tid << 4), k2g + g0);
        } else {
#pragma unroll
            for (int u2 = 0; u2 < 4; ++u2) {
                int gg = g0 + u2;
                k2s[buf * 128 + tid * 4 + u2] = (gg < NM) ? __ldg(k2g + gg) : F_INF;
            }
        }
    }
    asm volatile("cp.async.commit_group;\n" ::: "memory");
}

__global__ void __launch_bounds__(512, 1)
p1_kernel(const float* __restrict__ q, const __nv_bfloat16* __restrict__ keys16,
          const float* __restrict__ k2g, __half* __restrict__ dist,
          __half* __restrict__ tmin) {
    extern __shared__ __align__(16) char sm[];
    const uint32_t sb = smem_u32(sm);
    float* k2s = (float*)(sm + SM_K2);
    const unsigned FULL = 0xffffffffu;

    const int tid = threadIdx.x;
    const int w = tid >> 5;
    const int lt = tid & 31;
    const int wr = w & 7;          // q-row group
    const int wh = w >> 3;         // key half (0/1)

    const int it0 = blockIdx.x * 5;
    const int it1 = min(it0 + 5, NITEM);

    const int nbase = (lt >> 4) * 8 + (lt & 7);
    const int hh = (lt >> 3) & 1;
    const int r0 = wr * 16 + (lt >> 2);
    const int cbase = (lt & 3) << 1;

    uint32_t af[8][4];
    int cur_qb = -1;
    __half* drow0 = dist;
    __half* drow1 = dist;
    size_t trow = 0;

    for (int item = it0; item < it1; ++item) {
        const int qb = item / NCHK;
        const int chunk = item - qb * NCHK;
        const int gbase = chunk * CHT;

        if (qb != cur_qb) {
            __syncthreads();   // all warps done with previous staging/compute
            // stage q block as bf16 (swizzled)
#pragma unroll
            for (int itr = 0; itr < 4; ++itr) {
                int idx = tid + (itr << 9);
                int row = idx >> 4, u = idx & 15;
                const float* src = q + (size_t)(qb * 128 + row) * ND + u * 8;
                float4 v0 = *(const float4*)src;
                float4 v1 = *(const float4*)(src + 4);
                __nv_bfloat162 p0 = __floats2bfloat162_rn(v0.x, v0.y);
                __nv_bfloat162 p1 = __floats2bfloat162_rn(v0.z, v0.w);
                __nv_bfloat162 p2 = __floats2bfloat162_rn(v1.x, v1.y);
                __nv_bfloat162 p3 = __floats2bfloat162_rn(v1.z, v1.w);
                uint4 pk;
                pk.x = *(uint32_t*)&p0; pk.y = *(uint32_t*)&p1;
                pk.z = *(uint32_t*)&p2; pk.w = *(uint32_t*)&p3;
                *(uint4*)(sm + SM_QS + row * 256 + ((u ^ (row & 7)) << 4)) = pk;
            }
            __syncthreads();
            {
                int mrow = wr * 16 + (lt & 7) + ((lt >> 3) & 1) * 8;
                int kh = lt >> 4;
                uint32_t abase = sb + SM_QS + mrow * 256;
                int msw = mrow & 7;
#pragma unroll
                for (int kk = 0; kk < 8; ++kk)
                    ldsm_x4(af[kk][0], af[kk][1], af[kk][2], af[kk][3],
                            abase + ((((kk << 1) | kh) ^ msw) << 4));
            }
            cur_qb = qb;
            drow0 = dist + (size_t)(qb * 128 + r0) * NM;
            drow1 = drow0 + (size_t)8 * NM;
            trow = (size_t)(qb * 128 + r0) * NBLK;
        }

        p1_load_tile(gbase, 0, tid, sb, k2s, keys16, k2g);

        for (int tt = 0; tt < CHT; ++tt) {
            const int g = gbase + tt;
            const int buf = tt & 1;
            asm volatile("cp.async.wait_group 0;\n" ::: "memory");
            __syncthreads();
            if (tt + 1 < CHT) p1_load_tile(g + 1, (tt + 1) & 1, tid, sb, k2s, keys16, k2g);

            float acc[8][4];
#pragma unroll
            for (int j = 0; j < 8; ++j)
#pragma unroll
                for (int e = 0; e < 4; ++e) acc[j][e] = 0.f;

            const uint32_t bbase = sb + SM_B + buf * 32768 + wh * 16384;
#pragma unroll
            for (int kk = 0; kk < 8; ++kk) {
#pragma unroll
                for (int jp = 0; jp < 4; ++jp) {
                    int n = jp * 16 + nbase;
                    uint32_t addr = bbase + n * 256 + ((((kk << 1) | hh) ^ (n & 7)) << 4);
                    uint32_t b0, b1, b2, b3;
                    ldsm_x4(b0, b1, b2, b3, addr);
                    mma_bf16(acc[2 * jp], af[kk], b0, b1);
                    mma_bf16(acc[2 * jp + 1], af[kk], b2, b3);
                }
            }

            // stream scores (k2 - 2*dot) to HBM as fp16, tracking block minima
            const int m0t = g * TILEN;
            float mn0 = F_INF, mn1 = F_INF;
#pragma unroll
            for (int j = 0; j < 8; ++j) {
                int c = wh * 64 + j * 8 + cbase;
                int gc = m0t + c;
                if (gc < NM) {
                    float2 kk2 = *(float2*)(k2s + buf * 128 + c);
                    float2 s0, s1;
                    s0.x = fmaf(acc[j][0], -2.f, kk2.x);
                    s0.y = fmaf(acc[j][1], -2.f, kk2.y);
                    s1.x = fmaf(acc[j][2], -2.f, kk2.x);
                    s1.y = fmaf(acc[j][3], -2.f, kk2.y);
                    mn0 = fminf(mn0, fminf(s0.x, s0.y));
                    mn1 = fminf(mn1, fminf(s1.x, s1.y));
                    *(__half2*)(drow0 + gc) = __float22half2_rn(s0);
                    *(__half2*)(drow1 + gc) = __float22half2_rn(s1);
                }
            }
            mn0 = fminf(mn0, __shfl_xor_sync(FULL, mn0, 1));
            mn0 = fminf(mn0, __shfl_xor_sync(FULL, mn0, 2));
            mn1 = fminf(mn1, __shfl_xor_sync(FULL, mn1, 1));
            mn1 = fminf(mn1, __shfl_xor_sync(FULL, mn1, 2));
            if ((lt & 3) == 0) {
                size_t base = trow + g * 2 + wh;
                tmin[base] = __float2half(mn0);
                tmin[base + (size_t)8 * NBLK] = __float2half(mn1);
            }
        }
    }
}

// ---------------- selection: block-min prune + exact top-64 ---------------
__global__ void __launch_bounds__(256)
sel_kernel(const __half* __restrict__ dist, const __half* __restrict__ tmin,
           int* __restrict__ cand) {
    const unsigned FULL = 0xffffffffu;
    __shared__ int bids_s[8][64];
    const int wrp = threadIdx.x >> 5;
    const int wid = (blockIdx.x * blockDim.x + threadIdx.x) >> 5;  // row 0..4095
    const int lane = threadIdx.x & 31;

    // ---- pass A: top-64 of block minima (block b covers keys [b*64, b*64+64)) ----
    float s0 = F_INF, s1 = F_INF;
    int i0 = 0, i1 = 0;
    float mx = F_INF;
    const __half* trow = tmin + (size_t)wid * NBLK;
    for (int i = 0; i < 25; ++i) {
        int idx = i * 32 + lane;
        float fv = (idx < NBLK) ? __half2float(trow[idx]) : F_INF;
        if (__ballot_sync(FULL, fv < mx))
            ins64(s0, s1, i0, i1, mx, fv, idx, lane);
    }
    bids_s[wrp][lane * 2] = i0;
    bids_s[wrp][lane * 2 + 1] = i1;
    __syncwarp();

    // ---- pass B: exact top-64 over the 64 candidate blocks ----
    s0 = F_INF; s1 = F_INF; i0 = 0; i1 = 0; mx = F_INF;
    const __half* row = dist + (size_t)wid * NM;
    for (int b = 0; b < 64; ++b) {
        int key = bids_s[wrp][b] * 64 + lane * 2;
        float f0 = F_INF, f1 = F_INF;
        if (key < NM) {
            float2 ff = __half22float2(*(const __half2*)(row + key));
            f0 = ff.x; f1 = ff.y;
        }
        if (__ballot_sync(FULL, fminf(f0, f1) < mx)) {
            ins64(s0, s1, i0, i1, mx, f0, key, lane);
            ins64(s0, s1, i0, i1, mx, f1, key + 1, lane);
        }
    }
    int* dst = cand + (size_t)wid * 64;
    dst[lane * 2] = i0;
    dst[lane * 2 + 1] = i1;
}

// ---------------- phase 2: exact fp32 rescore + top-50 + output ------------
__global__ void __launch_bounds__(64)
p2_kernel(const float* __restrict__ q, const float* __restrict__ q2g,
          const float* __restrict__ k2g, const float* __restrict__ keys,
          const float* __restrict__ vals, const float* __restrict__ net,
          const int* __restrict__ cand, float* __restrict__ out) {
    __shared__ float qs[128];
    __shared__ float ds[64];
    __shared__ int isx[64];
    __shared__ float part[4];
    const int row = blockIdx.x;
    const int tid = threadIdx.x;
    qs[tid] = q[(size_t)row * ND + tid];
    qs[tid + 64] = q[(size_t)row * ND + tid + 64];
    __syncthreads();

    int c = cand[(size_t)row * 64 + tid];
    const float4* kr = (const float4*)(keys + (size_t)c * ND);
    float dot = 0.f;
#pragma unroll 8
    for (int i = 0; i < 32; ++i) {
        float4 k4 = kr[i];
        float4 q4 = *(const float4*)(qs + i * 4);
        dot = fmaf(k4.x, q4.x, dot);
        dot = fmaf(k4.y, q4.y, dot);
        dot = fmaf(k4.z, q4.z, dot);
        dot = fmaf(k4.w, q4.w, dot);
    }
    ds[tid] = q2g[row] + k2g[c] - 2.f * dot;
    isx[tid] = c;
    __syncthreads();

    // bitonic sort 64 by (dist, idx) ascending
    for (int k = 2; k <= 64; k <<= 1) {
        for (int j = k >> 1; j > 0; j >>= 1) {
            int p = tid ^ j;
            if (p > tid) {
                float d1 = ds[tid], d2 = ds[p];
                int i1 = isx[tid], i2 = isx[p];
                bool up = (tid & k) == 0;
                bool gt = (d1 > d2) || (d1 == d2 && i1 > i2);
                if (up ? gt : !gt) {
                    ds[tid] = d2; ds[p] = d1;
                    isx[tid] = i2; isx[p] = i1;
                }
            }
            __syncthreads();
        }
    }

    float wgt = 0.f, wv = 0.f;
    if (tid < NK) {
        wgt = 1.f / (ds[tid] + 1e-7f);
        wv = wgt * vals[isx[tid]];
    }
    float ws = warp_allred(wgt), vs = warp_allred(wv);
    if ((tid & 31) == 0) { part[tid >> 5] = ws; part[2 + (tid >> 5)] = vs; }
    __syncthreads();
    if (tid == 0) {
        float W = part[0] + part[1], V = part[2] + part[3];
        out[row] = 0.9f * (V / W) + 0.1f * net[row];
    }
}

// ---------------- launch (two-stream capturable DAG) ----------------
extern "C" void kernel_launch(void* const* d_in, const int* in_sizes, int n_in,
                              void* d_out, int out_size) {
    const float* states     = (const float*)d_in[0];
    const float* W1         = (const float*)d_in[1];
    const float* b1         = (const float*)d_in[2];
    const float* W2         = (const float*)d_in[3];
    const float* b2         = (const float*)d_in[4];
    const float* ln_g       = (const float*)d_in[5];
    const float* ln_b       = (const float*)d_in[6];
    const float* mem_keys   = (const float*)d_in[7];
    const float* mem_values = (const float*)d_in[8];
    const float* V1         = (const float*)d_in[9];
    const float* c1         = (const float*)d_in[10];
    const float* V2         = (const float*)d_in[11];
    const float* c2         = (const float*)d_in[12];
    const float* V3         = (const float*)d_in[13];
    const float* c3         = (const float*)d_in[14];
    float* out = (float*)d_out;

    void *ph, *pqpre, *pq, *pq2, *pk2, *pv1, *pv2, *pnet, *pk16, *pdist, *ptmin, *pcand;
    cudaGetSymbolAddress(&ph, g_h);
    cudaGetSymbolAddress(&pqpre, g_qpre);
    cudaGetSymbolAddress(&pq, g_q);
    cudaGetSymbolAddress(&pq2, g_q2);
    cudaGetSymbolAddress(&pk2, g_k2);
    cudaGetSymbolAddress(&pv1, g_v1);
    cudaGetSymbolAddress(&pv2, g_v2);
    cudaGetSymbolAddress(&pnet, g_net);
    cudaGetSymbolAddress(&pk16, g_keys16);
    cudaGetSymbolAddress(&pdist, g_dist);
    cudaGetSymbolAddress(&ptmin, g_tmin);
    cudaGetSymbolAddress(&pcand, g_cand);

    cudaFuncSetAttribute(p1_kernel, cudaFuncAttributeMaxDynamicSharedMemorySize, SM_TOT);

    // fork side stream into the capture
    cudaEventRecord(g_e0, 0);
    cudaStreamWaitEvent(g_s1, g_e0, 0);

    // ---- side branch (s1): key prep, then V-network chain ----
    cvtk2_kernel<<<NM / 8, 256, 0, g_s1>>>(mem_keys, (__nv_bfloat16*)pk16, (float*)pk2);
    cudaEventRecord(g_ek, g_s1);
    gemmz_kernel<<<dim3(NH / 64, NB / 64, 1), 256, 0, g_s1>>>(
        states, states, V1, V1, c1, c1, (float*)pv1, (float*)pv1, 1, NB, NH, NS);
    gemmz_kernel<<<dim3(ND / 64, NB / 64, 1), 256, 0, g_s1>>>(
        (const float*)pv1, (const float*)pv1, V2, V2, c2, c2,
        (float*)pv2, (float*)pv2, 1, NB, ND, NH);
    net_kernel<<<NB / 8, 256, 0, g_s1>>>((const float*)pv2, V3, c3, (float*)pnet);
    cudaEventRecord(g_ev, g_s1);

    // ---- main branch: encoder -> p1 -> sel -> p2 ----
    gemmz_kernel<<<dim3(NH / 64, NB / 64, 1), 256>>>(
        states, states, W1, W1, b1, b1, (float*)ph, (float*)ph, 1, NB, NH, NS);
    gemmz_kernel<<<dim3(ND / 64, NB / 64, 1), 256>>>(
        (const float*)ph, (const float*)ph, W2, W2, b2, b2,
        (float*)pqpre, (float*)pqpre, 0, NB, ND, NH);
    ln_kernel<<<NB / 8, 256>>>((const float*)pqpre, ln_g, ln_b, (float*)pq, (float*)pq2);

    cudaStreamWaitEvent(0, g_ek, 0);   // keys16/k2 ready
    p1_kernel<<<148, 512, SM_TOT>>>((const float*)pq, (const __nv_bfloat16*)pk16,
                                    (const float*)pk2, (__half*)pdist, (__half*)ptmin);

    sel_kernel<<<NB / 8, 256>>>((const __half*)pdist, (const __half*)ptmin, (int*)pcand);

    cudaStreamWaitEvent(0, g_ev, 0);   // net ready (join side branch before last node)
    p2_kernel<<<NB, 64>>>((const float*)pq, (const float*)pq2, (const float*)pk2,
                          mem_keys, mem_values, (const float*)pnet,
                          (const int*)pcand, out);
}